// round 12
// baseline (speedup 1.0000x reference)
#include <cuda_runtime.h>
#include <cuda_fp16.h>
#include <float.h>
#include <stdint.h>

// ---------------------------------------------------------------------------
// Problem constants
// ---------------------------------------------------------------------------
#define BATCH   8
#define NP      4224
#define NSEQ    4223
#define TEXTL   128
#define IMGDIM  64
#define NHEAD   16
#define DHEAD   64
#define DIMC    1024
#define TRIPLE  3072
#define MROWS   (BATCH*NP)    // 33792
#define KTOT    1024
#define BK      64
#define NCHUNK  (KTOT / BK)   // 16

// Scratch (device globals — no allocation allowed)
__device__ __half  g_qkvh [(size_t)BATCH * NP * TRIPLE];  // q|k|v fp16 (207MB)
__device__ __half  g_a    [(size_t)MROWS * KTOT];         // A fp16 (x, then attn out)
__device__ __half  g_b_qkv[(size_t)TRIPLE * KTOT];        // w_qkv^T fp16
__device__ __half  g_b_out[(size_t)DIMC * KTOT];          // w_out^T fp16
__device__ uint8_t g_mask [BATCH * TEXTL];

// ---------------------------------------------------------------------------
// PTX helpers (baseline PTX only — compute_103 virtual arch)
// ---------------------------------------------------------------------------
__device__ __forceinline__ uint32_t smem_u32(const void* p) {
    uint32_t a;
    asm("{ .reg .u64 t; cvta.to.shared.u64 t, %1; cvt.u32.u64 %0, t; }" : "=r"(a) : "l"(p));
    return a;
}
__device__ __forceinline__ void mma16816(float d[4],
    uint32_t a0, uint32_t a1, uint32_t a2, uint32_t a3, uint32_t b0, uint32_t b1)
{
    asm volatile(
        "mma.sync.aligned.m16n8k16.row.col.f32.f16.f16.f32 "
        "{%0,%1,%2,%3},{%4,%5,%6,%7},{%8,%9},{%0,%1,%2,%3};\n"
        : "+f"(d[0]), "+f"(d[1]), "+f"(d[2]), "+f"(d[3])
        : "r"(a0), "r"(a1), "r"(a2), "r"(a3), "r"(b0), "r"(b1));
}
__device__ __forceinline__ void ldsm_x4(uint32_t r[4], uint32_t addr)
{
    asm volatile("ldmatrix.sync.aligned.m8n8.x4.shared.b16 {%0,%1,%2,%3}, [%4];"
                 : "=r"(r[0]), "=r"(r[1]), "=r"(r[2]), "=r"(r[3]) : "r"(addr));
}
__device__ __forceinline__ void ldsm_x4_t(uint32_t r[4], uint32_t addr)
{
    asm volatile("ldmatrix.sync.aligned.m8n8.x4.trans.shared.b16 {%0,%1,%2,%3}, [%4];"
                 : "=r"(r[0]), "=r"(r[1]), "=r"(r[2]), "=r"(r[3]) : "r"(addr));
}
__device__ __forceinline__ void ldsm_x2_t(uint32_t r[2], uint32_t addr)
{
    asm volatile("ldmatrix.sync.aligned.m8n8.x2.trans.shared.b16 {%0,%1}, [%2];"
                 : "=r"(r[0]), "=r"(r[1]) : "r"(addr));
}
__device__ __forceinline__ uint32_t pack_f16x2(float lo, float hi)
{
    uint32_t r;
    asm("cvt.rn.f16x2.f32 %0, %1, %2;" : "=r"(r) : "f"(hi), "f"(lo));
    return r;
}
__device__ __forceinline__ uint32_t ex2_f16x2(uint32_t h)
{
    uint32_t r;
    asm("ex2.approx.f16x2 %0, %1;" : "=r"(r) : "r"(h));
    return r;
}
__device__ __forceinline__ void cp_async16(uint32_t dst, const void* src)
{
    asm volatile("cp.async.cg.shared.global [%0], [%1], 16;" :: "r"(dst), "l"(src) : "memory");
}
#define CP_COMMIT()  asm volatile("cp.async.commit_group;" ::: "memory")
#define CP_WAIT(N)   asm volatile("cp.async.wait_group %0;" :: "n"(N) : "memory")

// ---------------------------------------------------------------------------
// Mask normalization (bool mask may arrive as int32 / float32 / uint8)
// ---------------------------------------------------------------------------
__global__ void normalize_mask_kernel(const void* __restrict__ mask_raw)
{
    __shared__ int cls;
    const uint32_t* w = (const uint32_t*)mask_raw;
    const uint8_t*  c = (const uint8_t*)mask_raw;
    if (threadIdx.x == 0) {
        bool all_int = true, all_f32 = true;
        for (int i = 0; i < 256; i++) {
            uint32_t v = w[i];
            if (v != 0u && v != 1u)          all_int = false;
            if (v != 0u && v != 0x3F800000u) all_f32 = false;
        }
        cls = (all_int || all_f32) ? 0 : 1;
    }
    __syncthreads();
    for (int i = threadIdx.x; i < BATCH * TEXTL; i += blockDim.x)
        g_mask[i] = (cls == 0) ? (w[i] != 0u) : (c[i] != 0u);
}

// ---------------------------------------------------------------------------
// A-side fp16 convert of x (with batch padding): g_a [MROWS][KTOT]
// ---------------------------------------------------------------------------
__global__ __launch_bounds__(256) void conv_a_kernel(const float* __restrict__ src)
{
    int idx = blockIdx.x * 256 + threadIdx.x;
    int m   = idx >> 8;
    int c4  = idx & 255;
    float4 v = make_float4(0.f, 0.f, 0.f, 0.f);
    {
        int b = m / NP, t = m - b * NP;
        if (t < NSEQ) v = *(const float4*)&src[((size_t)(b * NSEQ + t)) * KTOT + c4 * 4];
    }
    __half2 h01 = __floats2half2_rn(v.x, v.y);
    __half2 h23 = __floats2half2_rn(v.z, v.w);
    size_t off = (size_t)m * KTOT + c4 * 4;
    *(__half2*)&g_a[off]     = h01;
    *(__half2*)&g_a[off + 2] = h23;
}

// W-side: transpose + single-round fp16.  src [K][C] fp32 -> dst [C][K] fp16
__global__ __launch_bounds__(256) void conv_w_kernel(
    const float* __restrict__ src, __half* __restrict__ dst, int K, int C)
{
    __shared__ float tile[32][33];
    int c0 = blockIdx.x * 32, k0 = blockIdx.y * 32;
    int x = threadIdx.x, y = threadIdx.y;
#pragma unroll
    for (int i = 0; i < 32; i += 8)
        tile[y + i][x] = src[(size_t)(k0 + y + i) * C + c0 + x];
    __syncthreads();
#pragma unroll
    for (int i = 0; i < 32; i += 8)
        dst[(size_t)(c0 + y + i) * K + k0 + x] = __float2half_rn(tile[x][y + i]);
}

// ---------------------------------------------------------------------------
// fp16 tensor-core GEMM:  C[M,N] = A[M,1024] @ B[N,1024]^T  (single product)
// CTA 128x128, BK=64, 8 warps (2x4), warp tile 64x32, m16n8k16.
// 2-stage cp.async pipeline (R8 structure), 144B smem row stride.
// OUTH: fp16 output (GEMM1 -> g_qkvh); else fp32 (GEMM2 -> d_out, TRIM rows).
// ---------------------------------------------------------------------------
#define LSTRIDE   72                              // halves per smem row (144B)
#define ARR_ELEMS (128 * LSTRIDE)                 // 9216
#define STAGE_ELEMS (2 * ARR_ELEMS)               // A, B
#define SMEM_GEMM (2 * STAGE_ELEMS * 2)           // 73728 bytes

template <int NSTRIDE, bool TRIM, bool OUTH>
__global__ __launch_bounds__(256, 2)
void gemm_fp16_kernel(const __half* __restrict__ Ag,
                      const __half* __restrict__ Bg,
                      void* __restrict__ Cv)
{
    extern __shared__ __half sm[];
    const int tid  = threadIdx.x;
    const int bn   = blockIdx.x;
    const int bm   = blockIdx.y;
    const int warp = tid >> 5;
    const int lane = tid & 31;
    const int wm   = warp >> 2;
    const int wn   = warp & 3;
    const int g    = lane >> 2;
    const int t4   = lane & 3;

    float acc[4][4][4];
#pragma unroll
    for (int mi = 0; mi < 4; mi++)
#pragma unroll
        for (int ni = 0; ni < 4; ni++)
#pragma unroll
            for (int r = 0; r < 4; r++) acc[mi][ni][r] = 0.f;

    // loader: 2 threads per row; each covers 64B (4 cp16) of the 128B row
    const int ld_row = tid >> 1;
    const int ld_seg = (tid & 1);                 // 0 or 1, 32-half halves
    const __half* srcA = Ag + ((size_t)bm * 128 + ld_row) * KTOT + ld_seg * 32;
    const __half* srcB = Bg + ((size_t)bn * 128 + ld_row) * KTOT + ld_seg * 32;
    const uint32_t sm_row = smem_u32(sm) + (ld_row * LSTRIDE + ld_seg * 32) * 2;

    auto issue = [&](int kc) {
        const int buf = kc & 1;
        const int k0  = kc * BK;
        uint32_t dstA = sm_row + buf * (STAGE_ELEMS * 2);
        uint32_t dstB = dstA + ARR_ELEMS * 2;
#pragma unroll
        for (int q = 0; q < 4; q++) {
            cp_async16(dstA + q * 16, srcA + k0 + q * 8);
            cp_async16(dstB + q * 16, srcB + k0 + q * 8);
        }
        CP_COMMIT();
    };

    issue(0);

    const uint32_t smem0 = smem_u32(sm);
    const int a_row_off = (wm * 64 + (lane & 15)) * 144 + (lane >> 4) * 16;
    const int b_row_off = (wn * 32 + ((lane >> 4) << 3) + (lane & 7)) * 144
                        + ((lane >> 3) & 1) * 16;

    for (int kc = 0; kc < NCHUNK; kc++) {
        const int buf = kc & 1;
        if (kc + 1 < NCHUNK) { issue(kc + 1); CP_WAIT(1); }
        else                 { CP_WAIT(0); }
        __syncthreads();

        const uint32_t base = smem0 + buf * (STAGE_ELEMS * 2);
        const uint32_t aA = base;
        const uint32_t aB = base + ARR_ELEMS * 2;

#pragma unroll
        for (int ks = 0; ks < 4; ks++) {
            const int kb = ks * 32;               // 16 halves = 32B per k16 step
            uint32_t bf[2][4];
#pragma unroll
            for (int nip = 0; nip < 2; nip++)
                ldsm_x4(bf[nip], aB + b_row_off + nip * (16 * 144) + kb);
#pragma unroll
            for (int mi = 0; mi < 4; mi++) {
                uint32_t af[4];
                ldsm_x4(af, aA + a_row_off + mi * (16 * 144) + kb);
#pragma unroll
                for (int nip = 0; nip < 2; nip++) {
#pragma unroll
                    for (int s = 0; s < 2; s++) {
                        int ni = nip * 2 + s;
                        mma16816(acc[mi][ni], af[0],af[1],af[2],af[3],
                                 bf[nip][2*s], bf[nip][2*s+1]);
                    }
                }
            }
        }
        __syncthreads();
    }

    // ---- epilogue ----
#pragma unroll
    for (int mi = 0; mi < 4; mi++) {
#pragma unroll
        for (int half = 0; half < 2; half++) {
            int m = bm * 128 + wm * 64 + mi * 16 + g + half * 8;
            int ncol = bn * 128 + wn * 32 + t4 * 2;
            if (OUTH) {
                __half* dst = (__half*)Cv + (size_t)m * NSTRIDE + ncol;
#pragma unroll
                for (int ni = 0; ni < 4; ni++)
                    *(__half2*)&dst[ni * 8] =
                        __floats2half2_rn(acc[mi][ni][half*2], acc[mi][ni][half*2+1]);
            } else {
                float* dst = nullptr;
                if (TRIM) {
                    int b = m / NP, t = m - b * NP;
                    if (t < NSEQ) dst = (float*)Cv + ((size_t)(b * NSEQ + t)) * NSTRIDE + ncol;
                } else {
                    dst = (float*)Cv + (size_t)m * NSTRIDE + ncol;
                }
                if (dst) {
#pragma unroll
                    for (int ni = 0; ni < 4; ni++)
                        *(float2*)&dst[ni * 8] =
                            make_float2(acc[mi][ni][half*2], acc[mi][ni][half*2+1]);
                }
            }
        }
    }
}

// ---------------------------------------------------------------------------
// Attention epilogue helper: write o*inv as fp16 into g_a
// ---------------------------------------------------------------------------
__device__ __forceinline__ void store_attn_row(
    const float* o, float inv, size_t row, int h)
{
    size_t off = row * KTOT + h * DHEAD;
#pragma unroll
    for (int d = 0; d < 64; d += 2)
        *(__half2*)&g_a[off + d] = __floats2half2_rn(o[d] * inv, o[d + 1] * inv);
}

// ---------------------------------------------------------------------------
// Text attention: per (b,h), 128 queries x 128 keys, causal. fp16 source.
// ---------------------------------------------------------------------------
__global__ __launch_bounds__(128) void text_attn_kernel()
{
    extern __shared__ float smf[];
    float* KV = smf;
    float* S  = smf + 128 * 64;

    const int bh = blockIdx.x;
    const int b  = bh / NHEAD;
    const int h  = bh - b * NHEAD;
    const int i  = threadIdx.x;

    auto load_kv = [&](int part) {   // part: 1 = K, 2 = V
        for (int idx = threadIdx.x; idx < 128 * 8; idx += 128) {
            int t = idx >> 3, c8 = idx & 7;
            uint4 u = *(const uint4*)&g_qkvh[((size_t)(b * NP + t)) * TRIPLE
                                             + part * DIMC + h * DHEAD + c8 * 8];
            const __half2* p = (const __half2*)&u;
            float* dst = &KV[t * 64 + c8 * 8];
            float2 f0 = __half22float2(p[0]), f1 = __half22float2(p[1]);
            float2 f2 = __half22float2(p[2]), f3 = __half22float2(p[3]);
            dst[0]=f0.x; dst[1]=f0.y; dst[2]=f1.x; dst[3]=f1.y;
            dst[4]=f2.x; dst[5]=f2.y; dst[6]=f3.x; dst[7]=f3.y;
        }
    };

    load_kv(1);
    __syncthreads();

    float q[64];
    {
        const __half* qp = &g_qkvh[((size_t)(b * NP + i)) * TRIPLE + h * DHEAD];
#pragma unroll
        for (int d = 0; d < 64; d++) q[d] = __half2float(qp[d]) * 0.125f;
    }

    float mx = -FLT_MAX;
    for (int j = 0; j <= i; j++) {
        const float* kp = &KV[j * 64];
        float s0 = 0.f, s1 = 0.f, s2 = 0.f, s3 = 0.f;
#pragma unroll
        for (int d = 0; d < 64; d += 4) {
            s0 += q[d+0] * kp[d+0]; s1 += q[d+1] * kp[d+1];
            s2 += q[d+2] * kp[d+2]; s3 += q[d+3] * kp[d+3];
        }
        float s = (s0 + s1) + (s2 + s3);
        S[i * 128 + j] = s;
        mx = fmaxf(mx, s);
    }
    float sum = 0.f;
    for (int j = 0; j <= i; j++) {
        float p = __expf(S[i * 128 + j] - mx);
        S[i * 128 + j] = p;
        sum += p;
    }
    __syncthreads();

    load_kv(2);
    __syncthreads();

    float o[64];
#pragma unroll
    for (int d = 0; d < 64; d++) o[d] = 0.f;
    for (int j = 0; j <= i; j++) {
        float p = S[i * 128 + j];
        const float* vp = &KV[j * 64];
#pragma unroll
        for (int d = 0; d < 64; d++) o[d] += p * vp[d];
    }
    store_attn_row(o, 1.f / sum, (size_t)(b * NP + i), h);
}

// ---------------------------------------------------------------------------
// Image (axial) attention — tensor-core, fp16 source (straight 16B smem fills).
// ---------------------------------------------------------------------------
#define ISTR 72
#define SMEM_IMG ((64 + 192 + 192) * ISTR * 2 + 128)

__global__ __launch_bounds__(128) void img_attn_kernel()
{
    extern __shared__ __half sh[];
    __half*  Qs = sh;                        // 64 x 72
    __half*  Ks = sh + 64 * ISTR;            // 192 x 72
    __half*  Vs = sh + (64 + 192) * ISTR;    // 192 x 72 (cols 64..71 = ones)
    uint8_t* smask = (uint8_t*)(sh + (64 + 192 + 192) * ISTR);

    const int bid  = blockIdx.x;
    const int xr   = bid & 63;
    const int h    = (bid >> 6) & 15;
    const int b    = bid >> 10;
    const int tid  = threadIdx.x;
    const int warp = tid >> 5;
    const int lane = tid & 31;
    const int g    = lane >> 2;
    const int t4   = lane & 3;

    // ---- loads: Q (scaled, exact exponent shift), K, V ----
    const __half2 sc = __floats2half2_rn(0.125f, 0.125f);
    for (int idx = tid; idx < 64 * 8; idx += 128) {
        int r = idx >> 3, c8 = idx & 7;
        int tq = TEXTL + xr * 64 + r;
        uint4 u = *(const uint4*)&g_qkvh[((size_t)(b * NP + tq)) * TRIPLE + h * DHEAD + c8 * 8];
        __half2* p = (__half2*)&u;
#pragma unroll
        for (int z = 0; z < 4; z++) p[z] = __hmul2(p[z], sc);
        *(uint4*)&Qs[r * ISTR + c8 * 8] = u;
    }
    for (int idx = tid; idx < 192 * 8; idx += 128) {
        int r = idx >> 3, c8 = idx & 7;
        int t = (r < TEXTL) ? r : (TEXTL + xr * 64 + (r - TEXTL));
        *(uint4*)&Ks[r * ISTR + c8 * 8] =
            *(const uint4*)&g_qkvh[((size_t)(b * NP + t)) * TRIPLE + DIMC + h * DHEAD + c8 * 8];
    }
    for (int idx = tid; idx < 192 * 8; idx += 128) {
        int r = idx >> 3, c8 = idx & 7;
        int t = (r < TEXTL) ? r : (TEXTL + xr * 64 + (r - TEXTL));
        *(uint4*)&Vs[r * ISTR + c8 * 8] =
            *(const uint4*)&g_qkvh[((size_t)(b * NP + t)) * TRIPLE + 2 * DIMC + h * DHEAD + c8 * 8];
    }
    for (int idx = tid; idx < 192 * 4; idx += 128) {       // ones cols 64..71
        int r = idx >> 2, c = (idx & 3) * 2;
        *(__half2*)&Vs[r * ISTR + 64 + c] = __floats2half2_rn(1.f, 1.f);
    }
    for (int j = tid; j < TEXTL; j += 128) smask[j] = g_mask[b * TEXTL + j];
    __syncthreads();

    // ---- S = Q K^T : 24 n8-tiles ----
    float s_acc[24][4];
#pragma unroll
    for (int jt = 0; jt < 24; jt++)
#pragma unroll
        for (int r = 0; r < 4; r++) s_acc[jt][r] = 0.f;

    const uint32_t qbase = smem_u32(Qs) + (warp * 16 + (lane & 15)) * 144 + (lane >> 4) * 16;
    const uint32_t kbase = smem_u32(Ks) + (((lane >> 4) << 3) + (lane & 7)) * 144
                         + ((lane >> 3) & 1) * 16;
#pragma unroll
    for (int ks = 0; ks < 4; ks++) {
        uint32_t af[4];
        ldsm_x4(af, qbase + ks * 32);
#pragma unroll
        for (int jp = 0; jp < 12; jp++) {
            uint32_t bf[4];
            ldsm_x4(bf, kbase + jp * (16 * 144) + ks * 32);
            mma16816(s_acc[2*jp],   af[0],af[1],af[2],af[3], bf[0],bf[1]);
            mma16816(s_acc[2*jp+1], af[0],af[1],af[2],af[3], bf[2],bf[3]);
        }
    }

    // ---- masking ----
    const int rq0 = warp * 16 + g;
    const int rq1 = rq0 + 8;
#pragma unroll
    for (int jt = 0; jt < 16; jt++) {
        int c = jt * 8 + 2 * t4;
        if (!smask[c])   { s_acc[jt][0] = -1e30f; s_acc[jt][2] = -1e30f; }
        if (!smask[c+1]) { s_acc[jt][1] = -1e30f; s_acc[jt][3] = -1e30f; }
    }
#pragma unroll
    for (int jt = 16; jt < 24; jt++) {
        int c = (jt - 16) * 8 + 2 * t4;
        if (c     > rq0) s_acc[jt][0] = -1e30f;
        if (c + 1 > rq0) s_acc[jt][1] = -1e30f;
        if (c     > rq1) s_acc[jt][2] = -1e30f;
        if (c + 1 > rq1) s_acc[jt][3] = -1e30f;
    }

    // ---- row max ----
    float mx0 = -1e30f, mx1 = -1e30f;
#pragma unroll
    for (int jt = 0; jt < 24; jt++) {
        mx0 = fmaxf(mx0, fmaxf(s_acc[jt][0], s_acc[jt][1]));
        mx1 = fmaxf(mx1, fmaxf(s_acc[jt][2], s_acc[jt][3]));
    }
    mx0 = fmaxf(mx0, __shfl_xor_sync(0xffffffffu, mx0, 1));
    mx0 = fmaxf(mx0, __shfl_xor_sync(0xffffffffu, mx0, 2));
    mx1 = fmaxf(mx1, __shfl_xor_sync(0xffffffffu, mx1, 1));
    mx1 = fmaxf(mx1, __shfl_xor_sync(0xffffffffu, mx1, 2));

    // ---- P = exp2(S*log2e - mx*log2e) packed fp16 ----
    const float L2E = 1.44269504f;
    const float c0 = mx0 * L2E, c1 = mx1 * L2E;
    uint32_t p_lo[24], p_hi[24];
#pragma unroll
    for (int jt = 0; jt < 24; jt++) {
        float f0 = fmaf(s_acc[jt][0], L2E, -c0);
        float f1 = fmaf(s_acc[jt][1], L2E, -c0);
        float f2 = fmaf(s_acc[jt][2], L2E, -c1);
        float f3 = fmaf(s_acc[jt][3], L2E, -c1);
        p_lo[jt] = ex2_f16x2(pack_f16x2(f0, f1));
        p_hi[jt] = ex2_f16x2(pack_f16x2(f2, f3));
    }

    // ---- O = P V  (tile 8 = ones -> row sums) ----
    float o[9][4];
#pragma unroll
    for (int nt = 0; nt < 9; nt++)
#pragma unroll
        for (int r = 0; r < 4; r++) o[nt][r] = 0.f;

    const uint32_t vbase = smem_u32(Vs) + ((((lane >> 3) & 1) * 8) + (lane & 7)) * 144
                         + (lane >> 4) * 16;
    const uint32_t vones = smem_u32(Vs) + ((((lane >> 3) & 1) * 8) + (lane & 7)) * 144 + 128;
#pragma unroll
    for (int kt = 0; kt < 12; kt++) {
        uint32_t a0 = p_lo[2*kt], a1 = p_hi[2*kt], a2 = p_lo[2*kt+1], a3 = p_hi[2*kt+1];
#pragma unroll
        for (int np = 0; np < 4; np++) {
            uint32_t bf[4];
            ldsm_x4_t(bf, vbase + kt * (16 * 144) + np * 32);
            mma16816(o[2*np],   a0,a1,a2,a3, bf[0],bf[1]);
            mma16816(o[2*np+1], a0,a1,a2,a3, bf[2],bf[3]);
        }
        uint32_t bo[2];
        ldsm_x2_t(bo, vones + kt * (16 * 144));
        mma16816(o[8], a0,a1,a2,a3, bo[0],bo[1]);
    }

    // ---- epilogue: divide by sum, store fp16 into g_a ----
    const float inv0 = 1.f / o[8][0];
    const float inv1 = 1.f / o[8][2];
    const size_t row0 = ((size_t)(b * NP + TEXTL + xr * 64 + rq0)) * KTOT + h * DHEAD;
    const size_t row1 = row0 + 8 * KTOT;
#pragma unroll
    for (int nt = 0; nt < 8; nt++) {
        int c = nt * 8 + 2 * t4;
        *(__half2*)&g_a[row0 + c] = __floats2half2_rn(o[nt][0] * inv0, o[nt][1] * inv0);
        *(__half2*)&g_a[row1 + c] = __floats2half2_rn(o[nt][2] * inv1, o[nt][3] * inv1);
    }
}

// ---------------------------------------------------------------------------
// Launch
// ---------------------------------------------------------------------------
extern "C" void kernel_launch(void* const* d_in, const int* in_sizes, int n_in,
                              void* d_out, int out_size)
{
    const float* x     = nullptr;
    const void*  mask  = nullptr;
    const float* w_qkv = nullptr;
    const float* w_out = nullptr;
    for (int i = 0; i < n_in; i++) {
        long long sz = in_sizes[i];
        if      (sz == (long long)BATCH * NSEQ * DIMC) x     = (const float*)d_in[i];
        else if (sz == BATCH * TEXTL)                  mask  = d_in[i];
        else if (sz == (long long)DIMC * TRIPLE)       w_qkv = (const float*)d_in[i];
        else if (sz == (long long)DIMC * DIMC)         w_out = (const float*)d_in[i];
    }

    __half *a, *bq, *bo, *qkvh;
    cudaGetSymbolAddress((void**)&a,    g_a);
    cudaGetSymbolAddress((void**)&bq,   g_b_qkv);
    cudaGetSymbolAddress((void**)&bo,   g_b_out);
    cudaGetSymbolAddress((void**)&qkvh, g_qkvh);

    const int SMEM_TXT = 98304;
    cudaFuncSetAttribute(text_attn_kernel, cudaFuncAttributeMaxDynamicSharedMemorySize, SMEM_TXT);
    cudaFuncSetAttribute(img_attn_kernel,  cudaFuncAttributeMaxDynamicSharedMemorySize, SMEM_IMG);
    cudaFuncSetAttribute((const void*)gemm_fp16_kernel<TRIPLE, false, true>,
                         cudaFuncAttributeMaxDynamicSharedMemorySize, SMEM_GEMM);
    cudaFuncSetAttribute((const void*)gemm_fp16_kernel<DIMC, true, false>,
                         cudaFuncAttributeMaxDynamicSharedMemorySize, SMEM_GEMM);

    normalize_mask_kernel<<<1, 256>>>(mask);
    conv_w_kernel<<<dim3(TRIPLE / 32, KTOT / 32), dim3(32, 8)>>>(w_qkv, bq, KTOT, TRIPLE);
    conv_w_kernel<<<dim3(DIMC / 32,   KTOT / 32), dim3(32, 8)>>>(w_out, bo, KTOT, DIMC);
    conv_a_kernel<<<MROWS, 256>>>(x);

    dim3 g1(TRIPLE / 128, MROWS / 128);  // 24 x 264
    gemm_fp16_kernel<TRIPLE, false, true><<<g1, 256, SMEM_GEMM>>>(a, bq, qkvh);

    text_attn_kernel<<<BATCH * NHEAD, 128, SMEM_TXT>>>();
    img_attn_kernel<<<BATCH * NHEAD * IMGDIM, 128, SMEM_IMG>>>();

    dim3 g2(DIMC / 128, MROWS / 128);    // 8 x 264
    gemm_fp16_kernel<DIMC, true, false><<<g2, 256, SMEM_GEMM>>>(a, bo, d_out);
}

// round 13
// speedup vs baseline: 1.0678x; 1.0678x over previous
#include <cuda_runtime.h>
#include <cuda_fp16.h>
#include <float.h>
#include <stdint.h>

// ---------------------------------------------------------------------------
// Problem constants
// ---------------------------------------------------------------------------
#define BATCH   8
#define NP      4224
#define NSEQ    4223
#define TEXTL   128
#define IMGDIM  64
#define NHEAD   16
#define DHEAD   64
#define DIMC    1024
#define TRIPLE  3072
#define MROWS   (BATCH*NP)    // 33792
#define KTOT    1024
#define BK      32
#define NCHUNK  (KTOT / BK)

// Scratch (device globals — no allocation allowed)
__device__ __half  g_qkvh [(size_t)BATCH * NP * TRIPLE];  // q|k|v fp16 (207MB)
__device__ __half  g_a    [(size_t)MROWS * KTOT];         // A fp16 (x, then attn out)
__device__ __half  g_b_qkv[(size_t)TRIPLE * KTOT];        // w_qkv^T fp16
__device__ __half  g_b_out[(size_t)DIMC * KTOT];          // w_out^T fp16
__device__ uint8_t g_mask [BATCH * TEXTL];

// ---------------------------------------------------------------------------
// PTX helpers (baseline PTX only — compute_103 virtual arch)
// ---------------------------------------------------------------------------
__device__ __forceinline__ uint32_t smem_u32(const void* p) {
    uint32_t a;
    asm("{ .reg .u64 t; cvta.to.shared.u64 t, %1; cvt.u32.u64 %0, t; }" : "=r"(a) : "l"(p));
    return a;
}
__device__ __forceinline__ void mma16816(float d[4],
    uint32_t a0, uint32_t a1, uint32_t a2, uint32_t a3, uint32_t b0, uint32_t b1)
{
    asm volatile(
        "mma.sync.aligned.m16n8k16.row.col.f32.f16.f16.f32 "
        "{%0,%1,%2,%3},{%4,%5,%6,%7},{%8,%9},{%0,%1,%2,%3};\n"
        : "+f"(d[0]), "+f"(d[1]), "+f"(d[2]), "+f"(d[3])
        : "r"(a0), "r"(a1), "r"(a2), "r"(a3), "r"(b0), "r"(b1));
}
__device__ __forceinline__ void ldsm_x4(uint32_t r[4], uint32_t addr)
{
    asm volatile("ldmatrix.sync.aligned.m8n8.x4.shared.b16 {%0,%1,%2,%3}, [%4];"
                 : "=r"(r[0]), "=r"(r[1]), "=r"(r[2]), "=r"(r[3]) : "r"(addr));
}
__device__ __forceinline__ void ldsm_x4_t(uint32_t r[4], uint32_t addr)
{
    asm volatile("ldmatrix.sync.aligned.m8n8.x4.trans.shared.b16 {%0,%1,%2,%3}, [%4];"
                 : "=r"(r[0]), "=r"(r[1]), "=r"(r[2]), "=r"(r[3]) : "r"(addr));
}
__device__ __forceinline__ void ldsm_x2_t(uint32_t r[2], uint32_t addr)
{
    asm volatile("ldmatrix.sync.aligned.m8n8.x2.trans.shared.b16 {%0,%1}, [%2];"
                 : "=r"(r[0]), "=r"(r[1]) : "r"(addr));
}
__device__ __forceinline__ uint32_t pack_f16x2(float lo, float hi)
{
    uint32_t r;
    asm("cvt.rn.f16x2.f32 %0, %1, %2;" : "=r"(r) : "f"(hi), "f"(lo));
    return r;
}
__device__ __forceinline__ uint32_t ex2_f16x2(uint32_t h)
{
    uint32_t r;
    asm("ex2.approx.f16x2 %0, %1;" : "=r"(r) : "r"(h));
    return r;
}
__device__ __forceinline__ void cp_async16(uint32_t dst, const void* src)
{
    asm volatile("cp.async.cg.shared.global [%0], [%1], 16;" :: "r"(dst), "l"(src) : "memory");
}
#define CP_COMMIT()  asm volatile("cp.async.commit_group;" ::: "memory")
#define CP_WAIT(N)   asm volatile("cp.async.wait_group %0;" :: "n"(N) : "memory")

// ---------------------------------------------------------------------------
// Mask normalization (bool mask may arrive as int32 / float32 / uint8)
// ---------------------------------------------------------------------------
__global__ void normalize_mask_kernel(const void* __restrict__ mask_raw)
{
    __shared__ int cls;
    const uint32_t* w = (const uint32_t*)mask_raw;
    const uint8_t*  c = (const uint8_t*)mask_raw;
    if (threadIdx.x == 0) {
        bool all_int = true, all_f32 = true;
        for (int i = 0; i < 256; i++) {
            uint32_t v = w[i];
            if (v != 0u && v != 1u)          all_int = false;
            if (v != 0u && v != 0x3F800000u) all_f32 = false;
        }
        cls = (all_int || all_f32) ? 0 : 1;
    }
    __syncthreads();
    for (int i = threadIdx.x; i < BATCH * TEXTL; i += blockDim.x)
        g_mask[i] = (cls == 0) ? (w[i] != 0u) : (c[i] != 0u);
}

// ---------------------------------------------------------------------------
// A-side fp16 convert of x (with batch padding): g_a [MROWS][KTOT]
// ---------------------------------------------------------------------------
__global__ __launch_bounds__(256) void conv_a_kernel(const float* __restrict__ src)
{
    int idx = blockIdx.x * 256 + threadIdx.x;
    int m   = idx >> 8;
    int c4  = idx & 255;
    float4 v = make_float4(0.f, 0.f, 0.f, 0.f);
    {
        int b = m / NP, t = m - b * NP;
        if (t < NSEQ) v = *(const float4*)&src[((size_t)(b * NSEQ + t)) * KTOT + c4 * 4];
    }
    __half2 h01 = __floats2half2_rn(v.x, v.y);
    __half2 h23 = __floats2half2_rn(v.z, v.w);
    size_t off = (size_t)m * KTOT + c4 * 4;
    *(__half2*)&g_a[off]     = h01;
    *(__half2*)&g_a[off + 2] = h23;
}

// W-side: transpose + single-round fp16.  src [K][C] fp32 -> dst [C][K] fp16
__global__ __launch_bounds__(256) void conv_w_kernel(
    const float* __restrict__ src, __half* __restrict__ dst, int K, int C)
{
    __shared__ float tile[32][33];
    int c0 = blockIdx.x * 32, k0 = blockIdx.y * 32;
    int x = threadIdx.x, y = threadIdx.y;
#pragma unroll
    for (int i = 0; i < 32; i += 8)
        tile[y + i][x] = src[(size_t)(k0 + y + i) * C + c0 + x];
    __syncthreads();
#pragma unroll
    for (int i = 0; i < 32; i += 8)
        dst[(size_t)(c0 + y + i) * K + k0 + x] = __float2half_rn(tile[x][y + i]);
}

// ---------------------------------------------------------------------------
// fp16 tensor-core GEMM (R11 exact):  C[M,N] = A[M,1024] @ B[N,1024]^T
// CTA 128x128, BK=32, 8 warps (2x4), warp tile 64x32, m16n8k16.
// ---------------------------------------------------------------------------
#define LSTRIDE   40
#define ARR_ELEMS (128 * LSTRIDE)
#define STAGE_ELEMS (2 * ARR_ELEMS)               // A, B
#define SMEM_GEMM (2 * STAGE_ELEMS * 2)           // 40960 bytes

template <int NSTRIDE, bool TRIM, bool OUTH>
__global__ __launch_bounds__(256, 2)
void gemm_fp16_kernel(const __half* __restrict__ Ag,
                      const __half* __restrict__ Bg,
                      void* __restrict__ Cv)
{
    extern __shared__ __half sm[];
    const int tid  = threadIdx.x;
    const int bn   = blockIdx.x;
    const int bm   = blockIdx.y;
    const int warp = tid >> 5;
    const int lane = tid & 31;
    const int wm   = warp >> 2;
    const int wn   = warp & 3;
    const int g    = lane >> 2;
    const int t4   = lane & 3;

    float acc[4][4][4];
#pragma unroll
    for (int mi = 0; mi < 4; mi++)
#pragma unroll
        for (int ni = 0; ni < 4; ni++)
#pragma unroll
            for (int r = 0; r < 4; r++) acc[mi][ni][r] = 0.f;

    const int ld_row = tid >> 1;
    const int ld_seg = (tid & 1) * 2;
    const __half* srcA = Ag + ((size_t)bm * 128 + ld_row) * KTOT + ld_seg * 8;
    const __half* srcB = Bg + ((size_t)bn * 128 + ld_row) * KTOT + ld_seg * 8;
    const uint32_t sm_row = smem_u32(sm) + (ld_row * LSTRIDE + ld_seg * 8) * 2;

    auto issue = [&](int kc) {
        const int buf = kc & 1;
        const int k0  = kc * BK;
        uint32_t dst = sm_row + buf * (STAGE_ELEMS * 2);
        cp_async16(dst,                      srcA + k0);
        cp_async16(dst + 16,                 srcA + k0 + 8);
        cp_async16(dst + ARR_ELEMS * 2,      srcB + k0);
        cp_async16(dst + ARR_ELEMS * 2 + 16, srcB + k0 + 8);
        CP_COMMIT();
    };

    issue(0);

    const uint32_t smem0 = smem_u32(sm);
    const int a_row_off = (wm * 64 + (lane & 15)) * 80 + (lane >> 4) * 16;
    const int b_row_off = (wn * 32 + ((lane >> 4) << 3) + (lane & 7)) * 80
                        + ((lane >> 3) & 1) * 16;

    for (int kc = 0; kc < NCHUNK; kc++) {
        const int buf = kc & 1;
        if (kc + 1 < NCHUNK) { issue(kc + 1); CP_WAIT(1); }
        else                 { CP_WAIT(0); }
        __syncthreads();

        const uint32_t base = smem0 + buf * (STAGE_ELEMS * 2);
        const uint32_t aA = base;
        const uint32_t aB = base + ARR_ELEMS * 2;

#pragma unroll
        for (int ks = 0; ks < 2; ks++) {
            const int kb = ks * 32;
            uint32_t bf[2][4];
#pragma unroll
            for (int nip = 0; nip < 2; nip++)
                ldsm_x4(bf[nip], aB + b_row_off + nip * (16 * 80) + kb);
#pragma unroll
            for (int mi = 0; mi < 4; mi++) {
                uint32_t af[4];
                ldsm_x4(af, aA + a_row_off + mi * (16 * 80) + kb);
#pragma unroll
                for (int nip = 0; nip < 2; nip++) {
#pragma unroll
                    for (int s = 0; s < 2; s++) {
                        int ni = nip * 2 + s;
                        mma16816(acc[mi][ni], af[0],af[1],af[2],af[3],
                                 bf[nip][2*s], bf[nip][2*s+1]);
                    }
                }
            }
        }
        __syncthreads();
    }

    // ---- epilogue ----
#pragma unroll
    for (int mi = 0; mi < 4; mi++) {
#pragma unroll
        for (int half = 0; half < 2; half++) {
            int m = bm * 128 + wm * 64 + mi * 16 + g + half * 8;
            int ncol = bn * 128 + wn * 32 + t4 * 2;
            if (OUTH) {
                __half* dst = (__half*)Cv + (size_t)m * NSTRIDE + ncol;
#pragma unroll
                for (int ni = 0; ni < 4; ni++)
                    *(__half2*)&dst[ni * 8] =
                        __floats2half2_rn(acc[mi][ni][half*2], acc[mi][ni][half*2+1]);
            } else {
                float* dst = nullptr;
                if (TRIM) {
                    int b = m / NP, t = m - b * NP;
                    if (t < NSEQ) dst = (float*)Cv + ((size_t)(b * NSEQ + t)) * NSTRIDE + ncol;
                } else {
                    dst = (float*)Cv + (size_t)m * NSTRIDE + ncol;
                }
                if (dst) {
#pragma unroll
                    for (int ni = 0; ni < 4; ni++)
                        *(float2*)&dst[ni * 8] =
                            make_float2(acc[mi][ni][half*2], acc[mi][ni][half*2+1]);
                }
            }
        }
    }
}

// ---------------------------------------------------------------------------
// Attention epilogue helper: write o*inv as fp16 into g_a
// ---------------------------------------------------------------------------
__device__ __forceinline__ void store_attn_row(
    const float* o, float inv, size_t row, int h)
{
    size_t off = row * KTOT + h * DHEAD;
#pragma unroll
    for (int d = 0; d < 64; d += 2)
        *(__half2*)&g_a[off + d] = __floats2half2_rn(o[d] * inv, o[d + 1] * inv);
}

// ---------------------------------------------------------------------------
// Fused attention kernel: blocks [0,128) = text (b,h); blocks [128, 8320) = img.
// 128 threads per block; shared dynamic smem sized for the img path (64.6KB).
// ---------------------------------------------------------------------------
#define ISTR 72
#define SMEM_ATT ((64 + 192 + 192) * ISTR * 2 + 128)

__global__ __launch_bounds__(128) void attn_kernel()
{
    extern __shared__ __half sh[];
    const int tid  = threadIdx.x;

    if (blockIdx.x < 128) {
        // ================= TEXT path =================
        // per (b,h): 128 queries x 128 keys, causal. fp16 smem.
        __half* KVh = sh;                 // 128 x 64
        __half* Sh  = sh + 128 * 64;      // 128 x 128
        const int bh = blockIdx.x;
        const int b  = bh >> 4;
        const int h  = bh & 15;
        const int i  = tid;

        auto load_kv = [&](int part) {    // 1 = K, 2 = V (16B straight copies)
            for (int idx = tid; idx < 128 * 8; idx += 128) {
                int t = idx >> 3, c8 = idx & 7;
                *(uint4*)&KVh[t * 64 + c8 * 8] =
                    *(const uint4*)&g_qkvh[((size_t)(b * NP + t)) * TRIPLE
                                           + part * DIMC + h * DHEAD + c8 * 8];
            }
        };

        load_kv(1);
        __syncthreads();

        float q[64];
        {
            const __half* qp = &g_qkvh[((size_t)(b * NP + i)) * TRIPLE + h * DHEAD];
#pragma unroll
            for (int d = 0; d < 64; d++) q[d] = __half2float(qp[d]) * 0.125f;
        }

        auto dot64 = [&](int r) -> float {
            const uint4* kp = (const uint4*)&KVh[r * 64];
            float s0 = 0.f, s1 = 0.f, s2 = 0.f, s3 = 0.f;
#pragma unroll
            for (int w = 0; w < 8; w++) {
                uint4 u = kp[w];
                float2 f0 = __half22float2(*(__half2*)&u.x);
                float2 f1 = __half22float2(*(__half2*)&u.y);
                float2 f2 = __half22float2(*(__half2*)&u.z);
                float2 f3 = __half22float2(*(__half2*)&u.w);
                int d = w * 8;
                s0 += q[d+0] * f0.x; s1 += q[d+1] * f0.y;
                s2 += q[d+2] * f1.x; s3 += q[d+3] * f1.y;
                s0 += q[d+4] * f2.x; s1 += q[d+5] * f2.y;
                s2 += q[d+6] * f3.x; s3 += q[d+7] * f3.y;
            }
            return (s0 + s1) + (s2 + s3);
        };

        float mx = -FLT_MAX;
        for (int j = 0; j <= i; j++) {
            float s = dot64(j);
            Sh[i * 128 + j] = __float2half_rn(s);
            mx = fmaxf(mx, s);
        }
        float sum = 0.f;
        for (int j = 0; j <= i; j++) {
            float p = __expf(__half2float(Sh[i * 128 + j]) - mx);
            Sh[i * 128 + j] = __float2half_rn(p);
            sum += p;
        }
        __syncthreads();

        load_kv(2);
        __syncthreads();

        float o[64];
#pragma unroll
        for (int d = 0; d < 64; d++) o[d] = 0.f;
        for (int j = 0; j <= i; j++) {
            float p = __half2float(Sh[i * 128 + j]);
            const uint4* vp = (const uint4*)&KVh[j * 64];
#pragma unroll
            for (int w = 0; w < 8; w++) {
                uint4 u = vp[w];
                float2 f0 = __half22float2(*(__half2*)&u.x);
                float2 f1 = __half22float2(*(__half2*)&u.y);
                float2 f2 = __half22float2(*(__half2*)&u.z);
                float2 f3 = __half22float2(*(__half2*)&u.w);
                int d = w * 8;
                o[d+0] += p * f0.x; o[d+1] += p * f0.y;
                o[d+2] += p * f1.x; o[d+3] += p * f1.y;
                o[d+4] += p * f2.x; o[d+5] += p * f2.y;
                o[d+6] += p * f3.x; o[d+7] += p * f3.y;
            }
        }
        store_attn_row(o, 1.f / sum, (size_t)(b * NP + i), h);
        return;
    }

    // ================= IMAGE path (tensor-core) =================
    __half*  Qs = sh;                        // 64 x 72
    __half*  Ks = sh + 64 * ISTR;            // 192 x 72
    __half*  Vs = sh + (64 + 192) * ISTR;    // 192 x 72 (cols 64..71 = ones)
    uint8_t* smask = (uint8_t*)(sh + (64 + 192 + 192) * ISTR);

    const int bid  = blockIdx.x - 128;
    const int xr   = bid & 63;
    const int h    = (bid >> 6) & 15;
    const int b    = bid >> 10;
    const int warp = tid >> 5;
    const int lane = tid & 31;
    const int g    = lane >> 2;
    const int t4   = lane & 3;

    // ---- loads: Q (scaled, exact exponent shift), K, V ----
    const __half2 sc = __floats2half2_rn(0.125f, 0.125f);
    for (int idx = tid; idx < 64 * 8; idx += 128) {
        int r = idx >> 3, c8 = idx & 7;
        int tq = TEXTL + xr * 64 + r;
        uint4 u = *(const uint4*)&g_qkvh[((size_t)(b * NP + tq)) * TRIPLE + h * DHEAD + c8 * 8];
        __half2* p = (__half2*)&u;
#pragma unroll
        for (int z = 0; z < 4; z++) p[z] = __hmul2(p[z], sc);
        *(uint4*)&Qs[r * ISTR + c8 * 8] = u;
    }
    for (int idx = tid; idx < 192 * 8; idx += 128) {
        int r = idx >> 3, c8 = idx & 7;
        int t = (r < TEXTL) ? r : (TEXTL + xr * 64 + (r - TEXTL));
        *(uint4*)&Ks[r * ISTR + c8 * 8] =
            *(const uint4*)&g_qkvh[((size_t)(b * NP + t)) * TRIPLE + DIMC + h * DHEAD + c8 * 8];
    }
    for (int idx = tid; idx < 192 * 8; idx += 128) {
        int r = idx >> 3, c8 = idx & 7;
        int t = (r < TEXTL) ? r : (TEXTL + xr * 64 + (r - TEXTL));
        *(uint4*)&Vs[r * ISTR + c8 * 8] =
            *(const uint4*)&g_qkvh[((size_t)(b * NP + t)) * TRIPLE + 2 * DIMC + h * DHEAD + c8 * 8];
    }
    for (int idx = tid; idx < 192 * 4; idx += 128) {       // ones cols 64..71
        int r = idx >> 2, c = (idx & 3) * 2;
        *(__half2*)&Vs[r * ISTR + 64 + c] = __floats2half2_rn(1.f, 1.f);
    }
    for (int j = tid; j < TEXTL; j += 128) smask[j] = g_mask[b * TEXTL + j];
    __syncthreads();

    // ---- S = Q K^T : 24 n8-tiles ----
    float s_acc[24][4];
#pragma unroll
    for (int jt = 0; jt < 24; jt++)
#pragma unroll
        for (int r = 0; r < 4; r++) s_acc[jt][r] = 0.f;

    const uint32_t qbase = smem_u32(Qs) + (warp * 16 + (lane & 15)) * 144 + (lane >> 4) * 16;
    const uint32_t kbase = smem_u32(Ks) + (((lane >> 4) << 3) + (lane & 7)) * 144
                         + ((lane >> 3) & 1) * 16;
#pragma unroll
    for (int ks = 0; ks < 4; ks++) {
        uint32_t af[4];
        ldsm_x4(af, qbase + ks * 32);
#pragma unroll
        for (int jp = 0; jp < 12; jp++) {
            uint32_t bf[4];
            ldsm_x4(bf, kbase + jp * (16 * 144) + ks * 32);
            mma16816(s_acc[2*jp],   af[0],af[1],af[2],af[3], bf[0],bf[1]);
            mma16816(s_acc[2*jp+1], af[0],af[1],af[2],af[3], bf[2],bf[3]);
        }
    }

    // ---- masking ----
    const int rq0 = warp * 16 + g;
    const int rq1 = rq0 + 8;
#pragma unroll
    for (int jt = 0; jt < 16; jt++) {
        int c = jt * 8 + 2 * t4;
        if (!smask[c])   { s_acc[jt][0] = -1e30f; s_acc[jt][2] = -1e30f; }
        if (!smask[c+1]) { s_acc[jt][1] = -1e30f; s_acc[jt][3] = -1e30f; }
    }
#pragma unroll
    for (int jt = 16; jt < 24; jt++) {
        int c = (jt - 16) * 8 + 2 * t4;
        if (c     > rq0) s_acc[jt][0] = -1e30f;
        if (c + 1 > rq0) s_acc[jt][1] = -1e30f;
        if (c     > rq1) s_acc[jt][2] = -1e30f;
        if (c + 1 > rq1) s_acc[jt][3] = -1e30f;
    }

    // ---- row max ----
    float mx0 = -1e30f, mx1 = -1e30f;
#pragma unroll
    for (int jt = 0; jt < 24; jt++) {
        mx0 = fmaxf(mx0, fmaxf(s_acc[jt][0], s_acc[jt][1]));
        mx1 = fmaxf(mx1, fmaxf(s_acc[jt][2], s_acc[jt][3]));
    }
    mx0 = fmaxf(mx0, __shfl_xor_sync(0xffffffffu, mx0, 1));
    mx0 = fmaxf(mx0, __shfl_xor_sync(0xffffffffu, mx0, 2));
    mx1 = fmaxf(mx1, __shfl_xor_sync(0xffffffffu, mx1, 1));
    mx1 = fmaxf(mx1, __shfl_xor_sync(0xffffffffu, mx1, 2));

    // ---- P = exp2(S*log2e - mx*log2e) packed fp16 ----
    const float L2E = 1.44269504f;
    const float c0 = mx0 * L2E, c1 = mx1 * L2E;
    uint32_t p_lo[24], p_hi[24];
#pragma unroll
    for (int jt = 0; jt < 24; jt++) {
        float f0 = fmaf(s_acc[jt][0], L2E, -c0);
        float f1 = fmaf(s_acc[jt][1], L2E, -c0);
        float f2 = fmaf(s_acc[jt][2], L2E, -c1);
        float f3 = fmaf(s_acc[jt][3], L2E, -c1);
        p_lo[jt] = ex2_f16x2(pack_f16x2(f0, f1));
        p_hi[jt] = ex2_f16x2(pack_f16x2(f2, f3));
    }

    // ---- O = P V  (tile 8 = ones -> row sums) ----
    float o[9][4];
#pragma unroll
    for (int nt = 0; nt < 9; nt++)
#pragma unroll
        for (int r = 0; r < 4; r++) o[nt][r] = 0.f;

    const uint32_t vbase = smem_u32(Vs) + ((((lane >> 3) & 1) * 8) + (lane & 7)) * 144
                         + (lane >> 4) * 16;
    const uint32_t vones = smem_u32(Vs) + ((((lane >> 3) & 1) * 8) + (lane & 7)) * 144 + 128;
#pragma unroll
    for (int kt = 0; kt < 12; kt++) {
        uint32_t a0 = p_lo[2*kt], a1 = p_hi[2*kt], a2 = p_lo[2*kt+1], a3 = p_hi[2*kt+1];
#pragma unroll
        for (int np = 0; np < 4; np++) {
            uint32_t bf[4];
            ldsm_x4_t(bf, vbase + kt * (16 * 144) + np * 32);
            mma16816(o[2*np],   a0,a1,a2,a3, bf[0],bf[1]);
            mma16816(o[2*np+1], a0,a1,a2,a3, bf[2],bf[3]);
        }
        uint32_t bo[2];
        ldsm_x2_t(bo, vones + kt * (16 * 144));
        mma16816(o[8], a0,a1,a2,a3, bo[0],bo[1]);
    }

    // ---- epilogue: divide by sum, store fp16 into g_a ----
    const float inv0 = 1.f / o[8][0];
    const float inv1 = 1.f / o[8][2];
    const size_t row0 = ((size_t)(b * NP + TEXTL + xr * 64 + rq0)) * KTOT + h * DHEAD;
    const size_t row1 = row0 + 8 * KTOT;
#pragma unroll
    for (int nt = 0; nt < 8; nt++) {
        int c = nt * 8 + 2 * t4;
        *(__half2*)&g_a[row0 + c] = __floats2half2_rn(o[nt][0] * inv0, o[nt][1] * inv0);
        *(__half2*)&g_a[row1 + c] = __floats2half2_rn(o[nt][2] * inv1, o[nt][3] * inv1);
    }
}

// ---------------------------------------------------------------------------
// Launch
// ---------------------------------------------------------------------------
extern "C" void kernel_launch(void* const* d_in, const int* in_sizes, int n_in,
                              void* d_out, int out_size)
{
    const float* x     = nullptr;
    const void*  mask  = nullptr;
    const float* w_qkv = nullptr;
    const float* w_out = nullptr;
    for (int i = 0; i < n_in; i++) {
        long long sz = in_sizes[i];
        if      (sz == (long long)BATCH * NSEQ * DIMC) x     = (const float*)d_in[i];
        else if (sz == BATCH * TEXTL)                  mask  = d_in[i];
        else if (sz == (long long)DIMC * TRIPLE)       w_qkv = (const float*)d_in[i];
        else if (sz == (long long)DIMC * DIMC)         w_out = (const float*)d_in[i];
    }

    __half *a, *bq, *bo, *qkvh;
    cudaGetSymbolAddress((void**)&a,    g_a);
    cudaGetSymbolAddress((void**)&bq,   g_b_qkv);
    cudaGetSymbolAddress((void**)&bo,   g_b_out);
    cudaGetSymbolAddress((void**)&qkvh, g_qkvh);

    cudaFuncSetAttribute(attn_kernel, cudaFuncAttributeMaxDynamicSharedMemorySize, SMEM_ATT);
    cudaFuncSetAttribute((const void*)gemm_fp16_kernel<TRIPLE, false, true>,
                         cudaFuncAttributeMaxDynamicSharedMemorySize, SMEM_GEMM);
    cudaFuncSetAttribute((const void*)gemm_fp16_kernel<DIMC, true, false>,
                         cudaFuncAttributeMaxDynamicSharedMemorySize, SMEM_GEMM);

    normalize_mask_kernel<<<1, 256>>>(mask);
    conv_w_kernel<<<dim3(TRIPLE / 32, KTOT / 32), dim3(32, 8)>>>(w_qkv, bq, KTOT, TRIPLE);
    conv_w_kernel<<<dim3(DIMC / 32,   KTOT / 32), dim3(32, 8)>>>(w_out, bo, KTOT, DIMC);
    conv_a_kernel<<<MROWS, 256>>>(x);

    dim3 g1(TRIPLE / 128, MROWS / 128);  // 24 x 264
    gemm_fp16_kernel<TRIPLE, false, true><<<g1, 256, SMEM_GEMM>>>(a, bq, qkvh);

    attn_kernel<<<128 + BATCH * NHEAD * IMGDIM, 128, SMEM_ATT>>>();

    dim3 g2(DIMC / 128, MROWS / 128);    // 8 x 264
    gemm_fp16_kernel<DIMC, true, false><<<g2, 256, SMEM_GEMM>>>(a, bo, d_out);
}

// round 15
// speedup vs baseline: 1.0897x; 1.0204x over previous
#include <cuda_runtime.h>
#include <cuda_fp16.h>
#include <float.h>
#include <stdint.h>

// ---------------------------------------------------------------------------
// Problem constants
// ---------------------------------------------------------------------------
#define BATCH   8
#define NP      4224
#define NSEQ    4223
#define TEXTL   128
#define IMGDIM  64
#define NHEAD   16
#define DHEAD   64
#define DIMC    1024
#define TRIPLE  3072
#define MROWS   (BATCH*NP)    // 33792
#define KTOT    1024
#define BK      32
#define NCHUNK  (KTOT / BK)

// Scratch (device globals — no allocation allowed)
__device__ __half  g_qkvh [(size_t)BATCH * NP * TRIPLE];  // q|k|v fp16 (207MB)
__device__ __half  g_a    [(size_t)MROWS * KTOT];         // A fp16 (x, then attn out)
__device__ __half  g_b_qkv[(size_t)TRIPLE * KTOT];        // w_qkv^T fp16
__device__ __half  g_b_out[(size_t)DIMC * KTOT];          // w_out^T fp16
__device__ uint8_t g_mask [BATCH * TEXTL];

// ---------------------------------------------------------------------------
// PTX helpers (baseline PTX only — compute_103 virtual arch)
// ---------------------------------------------------------------------------
__device__ __forceinline__ uint32_t smem_u32(const void* p) {
    uint32_t a;
    asm("{ .reg .u64 t; cvta.to.shared.u64 t, %1; cvt.u32.u64 %0, t; }" : "=r"(a) : "l"(p));
    return a;
}
__device__ __forceinline__ void mma16816(float d[4],
    uint32_t a0, uint32_t a1, uint32_t a2, uint32_t a3, uint32_t b0, uint32_t b1)
{
    asm volatile(
        "mma.sync.aligned.m16n8k16.row.col.f32.f16.f16.f32 "
        "{%0,%1,%2,%3},{%4,%5,%6,%7},{%8,%9},{%0,%1,%2,%3};\n"
        : "+f"(d[0]), "+f"(d[1]), "+f"(d[2]), "+f"(d[3])
        : "r"(a0), "r"(a1), "r"(a2), "r"(a3), "r"(b0), "r"(b1));
}
__device__ __forceinline__ void ldsm_x4(uint32_t r[4], uint32_t addr)
{
    asm volatile("ldmatrix.sync.aligned.m8n8.x4.shared.b16 {%0,%1,%2,%3}, [%4];"
                 : "=r"(r[0]), "=r"(r[1]), "=r"(r[2]), "=r"(r[3]) : "r"(addr));
}
__device__ __forceinline__ void ldsm_x4_t(uint32_t r[4], uint32_t addr)
{
    asm volatile("ldmatrix.sync.aligned.m8n8.x4.trans.shared.b16 {%0,%1,%2,%3}, [%4];"
                 : "=r"(r[0]), "=r"(r[1]), "=r"(r[2]), "=r"(r[3]) : "r"(addr));
}
__device__ __forceinline__ void ldsm_x2_t(uint32_t r[2], uint32_t addr)
{
    asm volatile("ldmatrix.sync.aligned.m8n8.x2.trans.shared.b16 {%0,%1}, [%2];"
                 : "=r"(r[0]), "=r"(r[1]) : "r"(addr));
}
__device__ __forceinline__ uint32_t pack_f16x2(float lo, float hi)
{
    uint32_t r;
    asm("cvt.rn.f16x2.f32 %0, %1, %2;" : "=r"(r) : "f"(hi), "f"(lo));
    return r;
}
__device__ __forceinline__ uint32_t ex2_f16x2(uint32_t h)
{
    uint32_t r;
    asm("ex2.approx.f16x2 %0, %1;" : "=r"(r) : "r"(h));
    return r;
}
__device__ __forceinline__ void cp_async16(uint32_t dst, const void* src)
{
    asm volatile("cp.async.cg.shared.global [%0], [%1], 16;" :: "r"(dst), "l"(src) : "memory");
}
#define CP_COMMIT()  asm volatile("cp.async.commit_group;" ::: "memory")
#define CP_WAIT(N)   asm volatile("cp.async.wait_group %0;" :: "n"(N) : "memory")

// ---------------------------------------------------------------------------
// Mask normalization (bool mask may arrive as int32 / float32 / uint8)
// ---------------------------------------------------------------------------
__global__ void normalize_mask_kernel(const void* __restrict__ mask_raw)
{
    __shared__ int cls;
    const uint32_t* w = (const uint32_t*)mask_raw;
    const uint8_t*  c = (const uint8_t*)mask_raw;
    if (threadIdx.x == 0) {
        bool all_int = true, all_f32 = true;
        for (int i = 0; i < 256; i++) {
            uint32_t v = w[i];
            if (v != 0u && v != 1u)          all_int = false;
            if (v != 0u && v != 0x3F800000u) all_f32 = false;
        }
        cls = (all_int || all_f32) ? 0 : 1;
    }
    __syncthreads();
    for (int i = threadIdx.x; i < BATCH * TEXTL; i += blockDim.x)
        g_mask[i] = (cls == 0) ? (w[i] != 0u) : (c[i] != 0u);
}

// ---------------------------------------------------------------------------
// A-side fp16 convert of x (with batch padding): g_a [MROWS][KTOT]
// ---------------------------------------------------------------------------
__global__ __launch_bounds__(256) void conv_a_kernel(const float* __restrict__ src)
{
    int idx = blockIdx.x * 256 + threadIdx.x;
    int m   = idx >> 8;
    int c4  = idx & 255;
    float4 v = make_float4(0.f, 0.f, 0.f, 0.f);
    {
        int b = m / NP, t = m - b * NP;
        if (t < NSEQ) v = *(const float4*)&src[((size_t)(b * NSEQ + t)) * KTOT + c4 * 4];
    }
    __half2 h01 = __floats2half2_rn(v.x, v.y);
    __half2 h23 = __floats2half2_rn(v.z, v.w);
    size_t off = (size_t)m * KTOT + c4 * 4;
    *(__half2*)&g_a[off]     = h01;
    *(__half2*)&g_a[off + 2] = h23;
}

// W-side: transpose + single-round fp16.  src [K][C] fp32 -> dst [C][K] fp16
__global__ __launch_bounds__(256) void conv_w_kernel(
    const float* __restrict__ src, __half* __restrict__ dst, int K, int C)
{
    __shared__ float tile[32][33];
    int c0 = blockIdx.x * 32, k0 = blockIdx.y * 32;
    int x = threadIdx.x, y = threadIdx.y;
#pragma unroll
    for (int i = 0; i < 32; i += 8)
        tile[y + i][x] = src[(size_t)(k0 + y + i) * C + c0 + x];
    __syncthreads();
#pragma unroll
    for (int i = 0; i < 32; i += 8)
        dst[(size_t)(c0 + y + i) * K + k0 + x] = __float2half_rn(tile[x][y + i]);
}

// ---------------------------------------------------------------------------
// fp16 tensor-core GEMM (R11 exact):  C[M,N] = A[M,1024] @ B[N,1024]^T
// CTA 128x128, BK=32, 8 warps (2x4), warp tile 64x32, m16n8k16.
// ---------------------------------------------------------------------------
#define LSTRIDE   40
#define ARR_ELEMS (128 * LSTRIDE)
#define STAGE_ELEMS (2 * ARR_ELEMS)               // A, B
#define SMEM_GEMM (2 * STAGE_ELEMS * 2)           // 40960 bytes

template <int NSTRIDE, bool TRIM, bool OUTH>
__global__ __launch_bounds__(256, 2)
void gemm_fp16_kernel(const __half* __restrict__ Ag,
                      const __half* __restrict__ Bg,
                      void* __restrict__ Cv)
{
    extern __shared__ __half sm[];
    const int tid  = threadIdx.x;
    const int bn   = blockIdx.x;
    const int bm   = blockIdx.y;
    const int warp = tid >> 5;
    const int lane = tid & 31;
    const int wm   = warp >> 2;
    const int wn   = warp & 3;
    const int g    = lane >> 2;
    const int t4   = lane & 3;

    float acc[4][4][4];
#pragma unroll
    for (int mi = 0; mi < 4; mi++)
#pragma unroll
        for (int ni = 0; ni < 4; ni++)
#pragma unroll
            for (int r = 0; r < 4; r++) acc[mi][ni][r] = 0.f;

    const int ld_row = tid >> 1;
    const int ld_seg = (tid & 1) * 2;
    const __half* srcA = Ag + ((size_t)bm * 128 + ld_row) * KTOT + ld_seg * 8;
    const __half* srcB = Bg + ((size_t)bn * 128 + ld_row) * KTOT + ld_seg * 8;
    const uint32_t sm_row = smem_u32(sm) + (ld_row * LSTRIDE + ld_seg * 8) * 2;

    auto issue = [&](int kc) {
        const int buf = kc & 1;
        const int k0  = kc * BK;
        uint32_t dst = sm_row + buf * (STAGE_ELEMS * 2);
        cp_async16(dst,                      srcA + k0);
        cp_async16(dst + 16,                 srcA + k0 + 8);
        cp_async16(dst + ARR_ELEMS * 2,      srcB + k0);
        cp_async16(dst + ARR_ELEMS * 2 + 16, srcB + k0 + 8);
        CP_COMMIT();
    };

    issue(0);

    const uint32_t smem0 = smem_u32(sm);
    const int a_row_off = (wm * 64 + (lane & 15)) * 80 + (lane >> 4) * 16;
    const int b_row_off = (wn * 32 + ((lane >> 4) << 3) + (lane & 7)) * 80
                        + ((lane >> 3) & 1) * 16;

    for (int kc = 0; kc < NCHUNK; kc++) {
        const int buf = kc & 1;
        if (kc + 1 < NCHUNK) { issue(kc + 1); CP_WAIT(1); }
        else                 { CP_WAIT(0); }
        __syncthreads();

        const uint32_t base = smem0 + buf * (STAGE_ELEMS * 2);
        const uint32_t aA = base;
        const uint32_t aB = base + ARR_ELEMS * 2;

#pragma unroll
        for (int ks = 0; ks < 2; ks++) {
            const int kb = ks * 32;
            uint32_t bf[2][4];
#pragma unroll
            for (int nip = 0; nip < 2; nip++)
                ldsm_x4(bf[nip], aB + b_row_off + nip * (16 * 80) + kb);
#pragma unroll
            for (int mi = 0; mi < 4; mi++) {
                uint32_t af[4];
                ldsm_x4(af, aA + a_row_off + mi * (16 * 80) + kb);
#pragma unroll
                for (int nip = 0; nip < 2; nip++) {
#pragma unroll
                    for (int s = 0; s < 2; s++) {
                        int ni = nip * 2 + s;
                        mma16816(acc[mi][ni], af[0],af[1],af[2],af[3],
                                 bf[nip][2*s], bf[nip][2*s+1]);
                    }
                }
            }
        }
        __syncthreads();
    }

    // ---- epilogue ----
#pragma unroll
    for (int mi = 0; mi < 4; mi++) {
#pragma unroll
        for (int half = 0; half < 2; half++) {
            int m = bm * 128 + wm * 64 + mi * 16 + g + half * 8;
            int ncol = bn * 128 + wn * 32 + t4 * 2;
            if (OUTH) {
                __half* dst = (__half*)Cv + (size_t)m * NSTRIDE + ncol;
#pragma unroll
                for (int ni = 0; ni < 4; ni++)
                    *(__half2*)&dst[ni * 8] =
                        __floats2half2_rn(acc[mi][ni][half*2], acc[mi][ni][half*2+1]);
            } else {
                float* dst = nullptr;
                if (TRIM) {
                    int b = m / NP, t = m - b * NP;
                    if (t < NSEQ) dst = (float*)Cv + ((size_t)(b * NSEQ + t)) * NSTRIDE + ncol;
                } else {
                    dst = (float*)Cv + (size_t)m * NSTRIDE + ncol;
                }
                if (dst) {
#pragma unroll
                    for (int ni = 0; ni < 4; ni++)
                        *(float2*)&dst[ni * 8] =
                            make_float2(acc[mi][ni][half*2], acc[mi][ni][half*2+1]);
                }
            }
        }
    }
}

// ---------------------------------------------------------------------------
// Attention epilogue helper: write o*inv as fp16 into g_a
// ---------------------------------------------------------------------------
__device__ __forceinline__ void store_attn_row(
    const float* o, float inv, size_t row, int h)
{
    size_t off = row * KTOT + h * DHEAD;
#pragma unroll
    for (int d = 0; d < 64; d += 2)
        *(__half2*)&g_a[off + d] = __floats2half2_rn(o[d] * inv, o[d + 1] * inv);
}

// ---------------------------------------------------------------------------
// Fused attention kernel: blocks [0,128) = text (b,h); blocks [128, 8320) = img.
// 128 threads per block. Img path: Q fragments loaded DIRECTLY from gmem
// (no Q smem tile); K/V smem rows at 72-half (144B) stride (R13-proven).
// Smem 55.4KB -> 4 blocks/SM.
// ---------------------------------------------------------------------------
#define ISTR 72
#define SMEM_ATT ((192 + 192) * ISTR * 2 + 128)   // 55424

__global__ __launch_bounds__(128) void attn_kernel()
{
    extern __shared__ __half sh[];
    const int tid  = threadIdx.x;

    if (blockIdx.x < 128) {
        // ================= TEXT path =================
        __half* KVh = sh;                 // 128 x 64
        __half* Sh  = sh + 128 * 64;      // 128 x 128
        const int bh = blockIdx.x;
        const int b  = bh >> 4;
        const int h  = bh & 15;
        const int i  = tid;

        auto load_kv = [&](int part) {
            for (int idx = tid; idx < 128 * 8; idx += 128) {
                int t = idx >> 3, c8 = idx & 7;
                *(uint4*)&KVh[t * 64 + c8 * 8] =
                    *(const uint4*)&g_qkvh[((size_t)(b * NP + t)) * TRIPLE
                                           + part * DIMC + h * DHEAD + c8 * 8];
            }
        };

        load_kv(1);
        __syncthreads();

        float q[64];
        {
            const __half* qp = &g_qkvh[((size_t)(b * NP + i)) * TRIPLE + h * DHEAD];
#pragma unroll
            for (int d = 0; d < 64; d++) q[d] = __half2float(qp[d]) * 0.125f;
        }

        auto dot64 = [&](int r) -> float {
            const uint4* kp = (const uint4*)&KVh[r * 64];
            float s0 = 0.f, s1 = 0.f, s2 = 0.f, s3 = 0.f;
#pragma unroll
            for (int w = 0; w < 8; w++) {
                uint4 u = kp[w];
                float2 f0 = __half22float2(*(__half2*)&u.x);
                float2 f1 = __half22float2(*(__half2*)&u.y);
                float2 f2 = __half22float2(*(__half2*)&u.z);
                float2 f3 = __half22float2(*(__half2*)&u.w);
                int d = w * 8;
                s0 += q[d+0] * f0.x; s1 += q[d+1] * f0.y;
                s2 += q[d+2] * f1.x; s3 += q[d+3] * f1.y;
                s0 += q[d+4] * f2.x; s1 += q[d+5] * f2.y;
                s2 += q[d+6] * f3.x; s3 += q[d+7] * f3.y;
            }
            return (s0 + s1) + (s2 + s3);
        };

        float mx = -FLT_MAX;
        for (int j = 0; j <= i; j++) {
            float s = dot64(j);
            Sh[i * 128 + j] = __float2half_rn(s);
            mx = fmaxf(mx, s);
        }
        float sum = 0.f;
        for (int j = 0; j <= i; j++) {
            float p = __expf(__half2float(Sh[i * 128 + j]) - mx);
            Sh[i * 128 + j] = __float2half_rn(p);
            sum += p;
        }
        __syncthreads();

        load_kv(2);
        __syncthreads();

        float o[64];
#pragma unroll
        for (int d = 0; d < 64; d++) o[d] = 0.f;
        for (int j = 0; j <= i; j++) {
            float p = __half2float(Sh[i * 128 + j]);
            const uint4* vp = (const uint4*)&KVh[j * 64];
#pragma unroll
            for (int w = 0; w < 8; w++) {
                uint4 u = vp[w];
                float2 f0 = __half22float2(*(__half2*)&u.x);
                float2 f1 = __half22float2(*(__half2*)&u.y);
                float2 f2 = __half22float2(*(__half2*)&u.z);
                float2 f3 = __half22float2(*(__half2*)&u.w);
                int d = w * 8;
                o[d+0] += p * f0.x; o[d+1] += p * f0.y;
                o[d+2] += p * f1.x; o[d+3] += p * f1.y;
                o[d+4] += p * f2.x; o[d+5] += p * f2.y;
                o[d+6] += p * f3.x; o[d+7] += p * f3.y;
            }
        }
        store_attn_row(o, 1.f / sum, (size_t)(b * NP + i), h);
        return;
    }

    // ================= IMAGE path (tensor-core) =================
    __half*  Ks = sh;                        // 192 x 72
    __half*  Vs = sh + 192 * ISTR;           // 192 x 72 (cols 64..71 = ones)
    uint8_t* smask = (uint8_t*)(Vs + 192 * ISTR);

    const int bid  = blockIdx.x - 128;
    const int xr   = bid & 63;
    const int h    = (bid >> 6) & 15;
    const int b    = bid >> 10;
    const int warp = tid >> 5;
    const int lane = tid & 31;
    const int g    = lane >> 2;
    const int t4   = lane & 3;

    // ---- loads: K, V into smem; Q stays in gmem (fragment-direct) ----
    for (int idx = tid; idx < 192 * 8; idx += 128) {
        int r = idx >> 3, c8 = idx & 7;
        int t = (r < TEXTL) ? r : (TEXTL + xr * 64 + (r - TEXTL));
        *(uint4*)&Ks[r * ISTR + c8 * 8] =
            *(const uint4*)&g_qkvh[((size_t)(b * NP + t)) * TRIPLE + DIMC + h * DHEAD + c8 * 8];
    }
    for (int idx = tid; idx < 192 * 8; idx += 128) {
        int r = idx >> 3, c8 = idx & 7;
        int t = (r < TEXTL) ? r : (TEXTL + xr * 64 + (r - TEXTL));
        *(uint4*)&Vs[r * ISTR + c8 * 8] =
            *(const uint4*)&g_qkvh[((size_t)(b * NP + t)) * TRIPLE + 2 * DIMC + h * DHEAD + c8 * 8];
    }
    for (int idx = tid; idx < 192 * 4; idx += 128) {       // ones cols 64..71
        int r = idx >> 2, c = (idx & 3) * 2;
        *(__half2*)&Vs[r * ISTR + 64 + c] = __floats2half2_rn(1.f, 1.f);
    }
    for (int j = tid; j < TEXTL; j += 128) smask[j] = g_mask[b * TEXTL + j];
    __syncthreads();

    // ---- S = Q K^T : 24 n8-tiles; Q fragments straight from gmem ----
    float s_acc[24][4];
#pragma unroll
    for (int jt = 0; jt < 24; jt++)
#pragma unroll
        for (int r = 0; r < 4; r++) s_acc[jt][r] = 0.f;

    // Q rows for this warp start at global token TEXTL + xr*64 + warp*16
    const __half* Qrow = &g_qkvh[((size_t)(b * NP + TEXTL + xr * 64 + warp * 16)) * TRIPLE
                                 + h * DHEAD];
    const __half2 qsc = __floats2half2_rn(0.125f, 0.125f);
    const uint32_t kbase = smem_u32(Ks) + (((lane >> 4) << 3) + (lane & 7)) * 144
                         + ((lane >> 3) & 1) * 16;
#pragma unroll
    for (int ks = 0; ks < 4; ks++) {
        // A-fragment direct loads: a0=Q[g][16ks+2t4], a1=Q[g+8][..], a2=+8, a3=both
        const __half* qp = Qrow + (size_t)g * TRIPLE + ks * 16 + 2 * t4;
        uint32_t af[4];
        af[0] = *(const uint32_t*)qp;
        af[1] = *(const uint32_t*)(qp + 8 * TRIPLE);
        af[2] = *(const uint32_t*)(qp + 8);
        af[3] = *(const uint32_t*)(qp + 8 * TRIPLE + 8);
#pragma unroll
        for (int z = 0; z < 4; z++) {
            __half2 hv = __hmul2(*(__half2*)&af[z], qsc);
            af[z] = *(uint32_t*)&hv;
        }
#pragma unroll
        for (int jp = 0; jp < 12; jp++) {
            uint32_t bf[4];
            ldsm_x4(bf, kbase + jp * (16 * 144) + ks * 32);
            mma16816(s_acc[2*jp],   af[0],af[1],af[2],af[3], bf[0],bf[1]);
            mma16816(s_acc[2*jp+1], af[0],af[1],af[2],af[3], bf[2],bf[3]);
        }
    }

    // ---- masking ----
    const int rq0 = warp * 16 + g;
    const int rq1 = rq0 + 8;
#pragma unroll
    for (int jt = 0; jt < 16; jt++) {
        int c = jt * 8 + 2 * t4;
        if (!smask[c])   { s_acc[jt][0] = -1e30f; s_acc[jt][2] = -1e30f; }
        if (!smask[c+1]) { s_acc[jt][1] = -1e30f; s_acc[jt][3] = -1e30f; }
    }
#pragma unroll
    for (int jt = 16; jt < 24; jt++) {
        int c = (jt - 16) * 8 + 2 * t4;
        if (c     > rq0) s_acc[jt][0] = -1e30f;
        if (c + 1 > rq0) s_acc[jt][1] = -1e30f;
        if (c     > rq1) s_acc[jt][2] = -1e30f;
        if (c + 1 > rq1) s_acc[jt][3] = -1e30f;
    }

    // ---- row max ----
    float mx0 = -1e30f, mx1 = -1e30f;
#pragma unroll
    for (int jt = 0; jt < 24; jt++) {
        mx0 = fmaxf(mx0, fmaxf(s_acc[jt][0], s_acc[jt][1]));
        mx1 = fmaxf(mx1, fmaxf(s_acc[jt][2], s_acc[jt][3]));
    }
    mx0 = fmaxf(mx0, __shfl_xor_sync(0xffffffffu, mx0, 1));
    mx0 = fmaxf(mx0, __shfl_xor_sync(0xffffffffu, mx0, 2));
    mx1 = fmaxf(mx1, __shfl_xor_sync(0xffffffffu, mx1, 1));
    mx1 = fmaxf(mx1, __shfl_xor_sync(0xffffffffu, mx1, 2));

    // ---- P = exp2(S*log2e - mx*log2e) packed fp16 ----
    const float L2E = 1.44269504f;
    const float c0 = mx0 * L2E, c1 = mx1 * L2E;
    uint32_t p_lo[24], p_hi[24];
#pragma unroll
    for (int jt = 0; jt < 24; jt++) {
        float f0 = fmaf(s_acc[jt][0], L2E, -c0);
        float f1 = fmaf(s_acc[jt][1], L2E, -c0);
        float f2 = fmaf(s_acc[jt][2], L2E, -c1);
        float f3 = fmaf(s_acc[jt][3], L2E, -c1);
        p_lo[jt] = ex2_f16x2(pack_f16x2(f0, f1));
        p_hi[jt] = ex2_f16x2(pack_f16x2(f2, f3));
    }

    // ---- O = P V  (tile 8 = ones -> row sums) ----
    float o[9][4];
#pragma unroll
    for (int nt = 0; nt < 9; nt++)
#pragma unroll
        for (int r = 0; r < 4; r++) o[nt][r] = 0.f;

    const uint32_t vbase = smem_u32(Vs) + ((((lane >> 3) & 1) * 8) + (lane & 7)) * 144
                         + (lane >> 4) * 16;
    const uint32_t vones = smem_u32(Vs) + ((((lane >> 3) & 1) * 8) + (lane & 7)) * 144 + 128;
#pragma unroll
    for (int kt = 0; kt < 12; kt++) {
        uint32_t a0 = p_lo[2*kt], a1 = p_hi[2*kt], a2 = p_lo[2*kt+1], a3 = p_hi[2*kt+1];
#pragma unroll
        for (int np = 0; np < 4; np++) {
            uint32_t bf[4];
            ldsm_x4_t(bf, vbase + kt * (16 * 144) + np * 32);
            mma16816(o[2*np],   a0,a1,a2,a3, bf[0],bf[1]);
            mma16816(o[2*np+1], a0,a1,a2,a3, bf[2],bf[3]);
        }
        uint32_t bo[2];
        ldsm_x2_t(bo, vones + kt * (16 * 144));
        mma16816(o[8], a0,a1,a2,a3, bo[0],bo[1]);
    }

    // ---- epilogue: divide by sum, store fp16 into g_a ----
    const float inv0 = 1.f / o[8][0];
    const float inv1 = 1.f / o[8][2];
    const size_t row0 = ((size_t)(b * NP + TEXTL + xr * 64 + rq0)) * KTOT + h * DHEAD;
    const size_t row1 = row0 + 8 * KTOT;
#pragma unroll
    for (int nt = 0; nt < 8; nt++) {
        int c = nt * 8 + 2 * t4;
        *(__half2*)&g_a[row0 + c] = __floats2half2_rn(o[nt][0] * inv0, o[nt][1] * inv0);
        *(__half2*)&g_a[row1 + c] = __floats2half2_rn(o[nt][2] * inv1, o[nt][3] * inv1);
    }
}

// ---------------------------------------------------------------------------
// Launch
// ---------------------------------------------------------------------------
extern "C" void kernel_launch(void* const* d_in, const int* in_sizes, int n_in,
                              void* d_out, int out_size)
{
    const float* x     = nullptr;
    const void*  mask  = nullptr;
    const float* w_qkv = nullptr;
    const float* w_out = nullptr;
    for (int i = 0; i < n_in; i++) {
        long long sz = in_sizes[i];
        if      (sz == (long long)BATCH * NSEQ * DIMC) x     = (const float*)d_in[i];
        else if (sz == BATCH * TEXTL)                  mask  = d_in[i];
        else if (sz == (long long)DIMC * TRIPLE)       w_qkv = (const float*)d_in[i];
        else if (sz == (long long)DIMC * DIMC)         w_out = (const float*)d_in[i];
    }

    __half *a, *bq, *bo, *qkvh;
    cudaGetSymbolAddress((void**)&a,    g_a);
    cudaGetSymbolAddress((void**)&bq,   g_b_qkv);
    cudaGetSymbolAddress((void**)&bo,   g_b_out);
    cudaGetSymbolAddress((void**)&qkvh, g_qkvh);

    cudaFuncSetAttribute(attn_kernel, cudaFuncAttributeMaxDynamicSharedMemorySize, SMEM_ATT);
    cudaFuncSetAttribute((const void*)gemm_fp16_kernel<TRIPLE, false, true>,
                         cudaFuncAttributeMaxDynamicSharedMemorySize, SMEM_GEMM);
    cudaFuncSetAttribute((const void*)gemm_fp16_kernel<DIMC, true, false>,
                         cudaFuncAttributeMaxDynamicSharedMemorySize, SMEM_GEMM);

    normalize_mask_kernel<<<1, 256>>>(mask);
    conv_w_kernel<<<dim3(TRIPLE / 32, KTOT / 32), dim3(32, 8)>>>(w_qkv, bq, KTOT, TRIPLE);
    conv_w_kernel<<<dim3(DIMC / 32,   KTOT / 32), dim3(32, 8)>>>(w_out, bo, KTOT, DIMC);
    conv_a_kernel<<<MROWS, 256>>>(x);

    dim3 g1(TRIPLE / 128, MROWS / 128);  // 24 x 264
    gemm_fp16_kernel<TRIPLE, false, true><<<g1, 256, SMEM_GEMM>>>(a, bq, qkvh);

    attn_kernel<<<128 + BATCH * NHEAD * IMGDIM, 128, SMEM_ATT>>>();

    dim3 g2(DIMC / 128, MROWS / 128);    // 8 x 264
    gemm_fp16_kernel<DIMC, true, false><<<g2, 256, SMEM_GEMM>>>(a, bo, d_out);
}

// round 16
// speedup vs baseline: 1.0960x; 1.0059x over previous
#include <cuda_runtime.h>
#include <cuda_fp16.h>
#include <float.h>
#include <stdint.h>

// ---------------------------------------------------------------------------
// Problem constants
// ---------------------------------------------------------------------------
#define BATCH   8
#define NP      4224
#define NSEQ    4223
#define TEXTL   128
#define IMGDIM  64
#define NHEAD   16
#define DHEAD   64
#define DIMC    1024
#define TRIPLE  3072
#define MROWS   (BATCH*NP)    // 33792
#define KTOT    1024
#define BK      32
#define NCHUNK  (KTOT / BK)

// Scratch (device globals — no allocation allowed)
__device__ __half  g_qkvh [(size_t)BATCH * NP * TRIPLE];  // q|k|v fp16 (207MB)
__device__ __half  g_a    [(size_t)MROWS * KTOT];         // A fp16 (x, then attn out)
__device__ __half  g_b_qkv[(size_t)TRIPLE * KTOT];        // w_qkv^T fp16
__device__ __half  g_b_out[(size_t)DIMC * KTOT];          // w_out^T fp16
__device__ uint8_t g_mask [BATCH * TEXTL];

// ---------------------------------------------------------------------------
// PTX helpers (baseline PTX only — compute_103 virtual arch)
// ---------------------------------------------------------------------------
__device__ __forceinline__ uint32_t smem_u32(const void* p) {
    uint32_t a;
    asm("{ .reg .u64 t; cvta.to.shared.u64 t, %1; cvt.u32.u64 %0, t; }" : "=r"(a) : "l"(p));
    return a;
}
__device__ __forceinline__ void mma16816(float d[4],
    uint32_t a0, uint32_t a1, uint32_t a2, uint32_t a3, uint32_t b0, uint32_t b1)
{
    asm volatile(
        "mma.sync.aligned.m16n8k16.row.col.f32.f16.f16.f32 "
        "{%0,%1,%2,%3},{%4,%5,%6,%7},{%8,%9},{%0,%1,%2,%3};\n"
        : "+f"(d[0]), "+f"(d[1]), "+f"(d[2]), "+f"(d[3])
        : "r"(a0), "r"(a1), "r"(a2), "r"(a3), "r"(b0), "r"(b1));
}
__device__ __forceinline__ void ldsm_x4(uint32_t r[4], uint32_t addr)
{
    asm volatile("ldmatrix.sync.aligned.m8n8.x4.shared.b16 {%0,%1,%2,%3}, [%4];"
                 : "=r"(r[0]), "=r"(r[1]), "=r"(r[2]), "=r"(r[3]) : "r"(addr));
}
__device__ __forceinline__ void ldsm_x4_t(uint32_t r[4], uint32_t addr)
{
    asm volatile("ldmatrix.sync.aligned.m8n8.x4.trans.shared.b16 {%0,%1,%2,%3}, [%4];"
                 : "=r"(r[0]), "=r"(r[1]), "=r"(r[2]), "=r"(r[3]) : "r"(addr));
}
__device__ __forceinline__ void ldsm_x2_t(uint32_t r[2], uint32_t addr)
{
    asm volatile("ldmatrix.sync.aligned.m8n8.x2.trans.shared.b16 {%0,%1}, [%2];"
                 : "=r"(r[0]), "=r"(r[1]) : "r"(addr));
}
__device__ __forceinline__ uint32_t pack_f16x2(float lo, float hi)
{
    uint32_t r;
    asm("cvt.rn.f16x2.f32 %0, %1, %2;" : "=r"(r) : "f"(hi), "f"(lo));
    return r;
}
__device__ __forceinline__ uint32_t ex2_f16x2(uint32_t h)
{
    uint32_t r;
    asm("ex2.approx.f16x2 %0, %1;" : "=r"(r) : "r"(h));
    return r;
}
__device__ __forceinline__ void cp_async16(uint32_t dst, const void* src)
{
    asm volatile("cp.async.cg.shared.global [%0], [%1], 16;" :: "r"(dst), "l"(src) : "memory");
}
#define CP_COMMIT()  asm volatile("cp.async.commit_group;" ::: "memory")
#define CP_WAIT(N)   asm volatile("cp.async.wait_group %0;" :: "n"(N) : "memory")

// ---------------------------------------------------------------------------
// Fused prep kernel (one launch):
//   blocks [0, 33792)            : conv_a  (x fp32 -> g_a fp16, padded rows)
//   blocks [33792, 36864)        : transpose+convert w_qkv -> g_b_qkv
//   blocks [36864, 37888)        : transpose+convert w_out -> g_b_out
//   block  37888                 : mask normalize
// All blocks 256 threads, fully independent.
// ---------------------------------------------------------------------------
#define PREP_A   MROWS                      // 33792
#define PREP_WQ  (PREP_A + (TRIPLE/32)*(KTOT/32))   // +3072 -> 36864
#define PREP_WO  (PREP_WQ + (DIMC/32)*(KTOT/32))    // +1024 -> 37888
#define PREP_N   (PREP_WO + 1)

__global__ __launch_bounds__(256) void prep_kernel(
    const float* __restrict__ x,
    const float* __restrict__ w_qkv,
    const float* __restrict__ w_out,
    const void*  __restrict__ mask_raw)
{
    const int blk = blockIdx.x;
    const int tid = threadIdx.x;

    if (blk < PREP_A) {
        // ---- conv_a: one float4 per thread ----
        int idx = blk * 256 + tid;
        int m   = idx >> 8;
        int c4  = idx & 255;
        float4 v = make_float4(0.f, 0.f, 0.f, 0.f);
        int b = m / NP, t = m - b * NP;
        if (t < NSEQ) v = *(const float4*)&x[((size_t)(b * NSEQ + t)) * KTOT + c4 * 4];
        __half2 h01 = __floats2half2_rn(v.x, v.y);
        __half2 h23 = __floats2half2_rn(v.z, v.w);
        size_t off = (size_t)m * KTOT + c4 * 4;
        *(__half2*)&g_a[off]     = h01;
        *(__half2*)&g_a[off + 2] = h23;
        return;
    }

    if (blk < PREP_WO) {
        // ---- transpose + fp16 convert of a weight matrix ----
        const bool  qkv = blk < PREP_WQ;
        const int   lb  = qkv ? (blk - PREP_A) : (blk - PREP_WQ);
        const int   C   = qkv ? TRIPLE : DIMC;
        const float* src = qkv ? w_qkv : w_out;
        __half*      dst = qkv ? g_b_qkv : g_b_out;
        const int   cb  = C / 32;
        const int   c0  = (lb % cb) * 32;
        const int   k0  = (lb / cb) * 32;
        const int   xx  = tid & 31;
        const int   yy  = tid >> 5;

        __shared__ float tile[32][33];
#pragma unroll
        for (int i = 0; i < 32; i += 8)
            tile[yy + i][xx] = src[(size_t)(k0 + yy + i) * C + c0 + xx];
        __syncthreads();
#pragma unroll
        for (int i = 0; i < 32; i += 8)
            dst[(size_t)(c0 + yy + i) * KTOT + k0 + xx] = __float2half_rn(tile[xx][yy + i]);
        return;
    }

    // ---- mask normalize ----
    __shared__ int cls;
    const uint32_t* w = (const uint32_t*)mask_raw;
    const uint8_t*  c = (const uint8_t*)mask_raw;
    if (tid == 0) {
        bool all_int = true, all_f32 = true;
        for (int i = 0; i < 256; i++) {
            uint32_t v = w[i];
            if (v != 0u && v != 1u)          all_int = false;
            if (v != 0u && v != 0x3F800000u) all_f32 = false;
        }
        cls = (all_int || all_f32) ? 0 : 1;
    }
    __syncthreads();
    for (int i = tid; i < BATCH * TEXTL; i += 256)
        g_mask[i] = (cls == 0) ? (w[i] != 0u) : (c[i] != 0u);
}

// ---------------------------------------------------------------------------
// fp16 tensor-core GEMM (R11 exact):  C[M,N] = A[M,1024] @ B[N,1024]^T
// CTA 128x128, BK=32, 8 warps (2x4), warp tile 64x32, m16n8k16.
// ---------------------------------------------------------------------------
#define LSTRIDE   40
#define ARR_ELEMS (128 * LSTRIDE)
#define STAGE_ELEMS (2 * ARR_ELEMS)               // A, B
#define SMEM_GEMM (2 * STAGE_ELEMS * 2)           // 40960 bytes

template <int NSTRIDE, bool TRIM, bool OUTH>
__global__ __launch_bounds__(256, 2)
void gemm_fp16_kernel(const __half* __restrict__ Ag,
                      const __half* __restrict__ Bg,
                      void* __restrict__ Cv)
{
    extern __shared__ __half sm[];
    const int tid  = threadIdx.x;
    const int bn   = blockIdx.x;
    const int bm   = blockIdx.y;
    const int warp = tid >> 5;
    const int lane = tid & 31;
    const int wm   = warp >> 2;
    const int wn   = warp & 3;
    const int g    = lane >> 2;
    const int t4   = lane & 3;

    float acc[4][4][4];
#pragma unroll
    for (int mi = 0; mi < 4; mi++)
#pragma unroll
        for (int ni = 0; ni < 4; ni++)
#pragma unroll
            for (int r = 0; r < 4; r++) acc[mi][ni][r] = 0.f;

    const int ld_row = tid >> 1;
    const int ld_seg = (tid & 1) * 2;
    const __half* srcA = Ag + ((size_t)bm * 128 + ld_row) * KTOT + ld_seg * 8;
    const __half* srcB = Bg + ((size_t)bn * 128 + ld_row) * KTOT + ld_seg * 8;
    const uint32_t sm_row = smem_u32(sm) + (ld_row * LSTRIDE + ld_seg * 8) * 2;

    auto issue = [&](int kc) {
        const int buf = kc & 1;
        const int k0  = kc * BK;
        uint32_t dst = sm_row + buf * (STAGE_ELEMS * 2);
        cp_async16(dst,                      srcA + k0);
        cp_async16(dst + 16,                 srcA + k0 + 8);
        cp_async16(dst + ARR_ELEMS * 2,      srcB + k0);
        cp_async16(dst + ARR_ELEMS * 2 + 16, srcB + k0 + 8);
        CP_COMMIT();
    };

    issue(0);

    const uint32_t smem0 = smem_u32(sm);
    const int a_row_off = (wm * 64 + (lane & 15)) * 80 + (lane >> 4) * 16;
    const int b_row_off = (wn * 32 + ((lane >> 4) << 3) + (lane & 7)) * 80
                        + ((lane >> 3) & 1) * 16;

    for (int kc = 0; kc < NCHUNK; kc++) {
        const int buf = kc & 1;
        if (kc + 1 < NCHUNK) { issue(kc + 1); CP_WAIT(1); }
        else                 { CP_WAIT(0); }
        __syncthreads();

        const uint32_t base = smem0 + buf * (STAGE_ELEMS * 2);
        const uint32_t aA = base;
        const uint32_t aB = base + ARR_ELEMS * 2;

#pragma unroll
        for (int ks = 0; ks < 2; ks++) {
            const int kb = ks * 32;
            uint32_t bf[2][4];
#pragma unroll
            for (int nip = 0; nip < 2; nip++)
                ldsm_x4(bf[nip], aB + b_row_off + nip * (16 * 80) + kb);
#pragma unroll
            for (int mi = 0; mi < 4; mi++) {
                uint32_t af[4];
                ldsm_x4(af, aA + a_row_off + mi * (16 * 80) + kb);
#pragma unroll
                for (int nip = 0; nip < 2; nip++) {
#pragma unroll
                    for (int s = 0; s < 2; s++) {
                        int ni = nip * 2 + s;
                        mma16816(acc[mi][ni], af[0],af[1],af[2],af[3],
                                 bf[nip][2*s], bf[nip][2*s+1]);
                    }
                }
            }
        }
        __syncthreads();
    }

    // ---- epilogue ----
#pragma unroll
    for (int mi = 0; mi < 4; mi++) {
#pragma unroll
        for (int half = 0; half < 2; half++) {
            int m = bm * 128 + wm * 64 + mi * 16 + g + half * 8;
            int ncol = bn * 128 + wn * 32 + t4 * 2;
            if (OUTH) {
                __half* dst = (__half*)Cv + (size_t)m * NSTRIDE + ncol;
#pragma unroll
                for (int ni = 0; ni < 4; ni++)
                    *(__half2*)&dst[ni * 8] =
                        __floats2half2_rn(acc[mi][ni][half*2], acc[mi][ni][half*2+1]);
            } else {
                float* dst = nullptr;
                if (TRIM) {
                    int b = m / NP, t = m - b * NP;
                    if (t < NSEQ) dst = (float*)Cv + ((size_t)(b * NSEQ + t)) * NSTRIDE + ncol;
                } else {
                    dst = (float*)Cv + (size_t)m * NSTRIDE + ncol;
                }
                if (dst) {
#pragma unroll
                    for (int ni = 0; ni < 4; ni++)
                        *(float2*)&dst[ni * 8] =
                            make_float2(acc[mi][ni][half*2], acc[mi][ni][half*2+1]);
                }
            }
        }
    }
}

// ---------------------------------------------------------------------------
// Attention epilogue helper: write o*inv as fp16 into g_a
// ---------------------------------------------------------------------------
__device__ __forceinline__ void store_attn_row(
    const float* o, float inv, size_t row, int h)
{
    size_t off = row * KTOT + h * DHEAD;
#pragma unroll
    for (int d = 0; d < 64; d += 2)
        *(__half2*)&g_a[off + d] = __floats2half2_rn(o[d] * inv, o[d + 1] * inv);
}

// ---------------------------------------------------------------------------
// Fused attention kernel (R15 exact): blocks [0,128) text; [128, 8320) img.
// Img path: Q fragments direct from gmem; K/V smem at 144B stride; 4 blocks/SM.
// ---------------------------------------------------------------------------
#define ISTR 72
#define SMEM_ATT ((192 + 192) * ISTR * 2 + 128)   // 55424

__global__ __launch_bounds__(128) void attn_kernel()
{
    extern __shared__ __half sh[];
    const int tid  = threadIdx.x;

    if (blockIdx.x < 128) {
        // ================= TEXT path =================
        __half* KVh = sh;                 // 128 x 64
        __half* Sh  = sh + 128 * 64;      // 128 x 128
        const int bh = blockIdx.x;
        const int b  = bh >> 4;
        const int h  = bh & 15;
        const int i  = tid;

        auto load_kv = [&](int part) {
            for (int idx = tid; idx < 128 * 8; idx += 128) {
                int t = idx >> 3, c8 = idx & 7;
                *(uint4*)&KVh[t * 64 + c8 * 8] =
                    *(const uint4*)&g_qkvh[((size_t)(b * NP + t)) * TRIPLE
                                           + part * DIMC + h * DHEAD + c8 * 8];
            }
        };

        load_kv(1);
        __syncthreads();

        float q[64];
        {
            const __half* qp = &g_qkvh[((size_t)(b * NP + i)) * TRIPLE + h * DHEAD];
#pragma unroll
            for (int d = 0; d < 64; d++) q[d] = __half2float(qp[d]) * 0.125f;
        }

        auto dot64 = [&](int r) -> float {
            const uint4* kp = (const uint4*)&KVh[r * 64];
            float s0 = 0.f, s1 = 0.f, s2 = 0.f, s3 = 0.f;
#pragma unroll
            for (int w = 0; w < 8; w++) {
                uint4 u = kp[w];
                float2 f0 = __half22float2(*(__half2*)&u.x);
                float2 f1 = __half22float2(*(__half2*)&u.y);
                float2 f2 = __half22float2(*(__half2*)&u.z);
                float2 f3 = __half22float2(*(__half2*)&u.w);
                int d = w * 8;
                s0 += q[d+0] * f0.x; s1 += q[d+1] * f0.y;
                s2 += q[d+2] * f1.x; s3 += q[d+3] * f1.y;
                s0 += q[d+4] * f2.x; s1 += q[d+5] * f2.y;
                s2 += q[d+6] * f3.x; s3 += q[d+7] * f3.y;
            }
            return (s0 + s1) + (s2 + s3);
        };

        float mx = -FLT_MAX;
        for (int j = 0; j <= i; j++) {
            float s = dot64(j);
            Sh[i * 128 + j] = __float2half_rn(s);
            mx = fmaxf(mx, s);
        }
        float sum = 0.f;
        for (int j = 0; j <= i; j++) {
            float p = __expf(__half2float(Sh[i * 128 + j]) - mx);
            Sh[i * 128 + j] = __float2half_rn(p);
            sum += p;
        }
        __syncthreads();

        load_kv(2);
        __syncthreads();

        float o[64];
#pragma unroll
        for (int d = 0; d < 64; d++) o[d] = 0.f;
        for (int j = 0; j <= i; j++) {
            float p = __half2float(Sh[i * 128 + j]);
            const uint4* vp = (const uint4*)&KVh[j * 64];
#pragma unroll
            for (int w = 0; w < 8; w++) {
                uint4 u = vp[w];
                float2 f0 = __half22float2(*(__half2*)&u.x);
                float2 f1 = __half22float2(*(__half2*)&u.y);
                float2 f2 = __half22float2(*(__half2*)&u.z);
                float2 f3 = __half22float2(*(__half2*)&u.w);
                int d = w * 8;
                o[d+0] += p * f0.x; o[d+1] += p * f0.y;
                o[d+2] += p * f1.x; o[d+3] += p * f1.y;
                o[d+4] += p * f2.x; o[d+5] += p * f2.y;
                o[d+6] += p * f3.x; o[d+7] += p * f3.y;
            }
        }
        store_attn_row(o, 1.f / sum, (size_t)(b * NP + i), h);
        return;
    }

    // ================= IMAGE path (tensor-core) =================
    __half*  Ks = sh;                        // 192 x 72
    __half*  Vs = sh + 192 * ISTR;           // 192 x 72 (cols 64..71 = ones)
    uint8_t* smask = (uint8_t*)(Vs + 192 * ISTR);

    const int bid  = blockIdx.x - 128;
    const int xr   = bid & 63;
    const int h    = (bid >> 6) & 15;
    const int b    = bid >> 10;
    const int warp = tid >> 5;
    const int lane = tid & 31;
    const int g    = lane >> 2;
    const int t4   = lane & 3;

    // ---- loads: K, V into smem; Q stays in gmem (fragment-direct) ----
    for (int idx = tid; idx < 192 * 8; idx += 128) {
        int r = idx >> 3, c8 = idx & 7;
        int t = (r < TEXTL) ? r : (TEXTL + xr * 64 + (r - TEXTL));
        *(uint4*)&Ks[r * ISTR + c8 * 8] =
            *(const uint4*)&g_qkvh[((size_t)(b * NP + t)) * TRIPLE + DIMC + h * DHEAD + c8 * 8];
    }
    for (int idx = tid; idx < 192 * 8; idx += 128) {
        int r = idx >> 3, c8 = idx & 7;
        int t = (r < TEXTL) ? r : (TEXTL + xr * 64 + (r - TEXTL));
        *(uint4*)&Vs[r * ISTR + c8 * 8] =
            *(const uint4*)&g_qkvh[((size_t)(b * NP + t)) * TRIPLE + 2 * DIMC + h * DHEAD + c8 * 8];
    }
    for (int idx = tid; idx < 192 * 4; idx += 128) {       // ones cols 64..71
        int r = idx >> 2, c = (idx & 3) * 2;
        *(__half2*)&Vs[r * ISTR + 64 + c] = __floats2half2_rn(1.f, 1.f);
    }
    for (int j = tid; j < TEXTL; j += 128) smask[j] = g_mask[b * TEXTL + j];
    __syncthreads();

    // ---- S = Q K^T : 24 n8-tiles; Q fragments straight from gmem ----
    float s_acc[24][4];
#pragma unroll
    for (int jt = 0; jt < 24; jt++)
#pragma unroll
        for (int r = 0; r < 4; r++) s_acc[jt][r] = 0.f;

    const __half* Qrow = &g_qkvh[((size_t)(b * NP + TEXTL + xr * 64 + warp * 16)) * TRIPLE
                                 + h * DHEAD];
    const __half2 qsc = __floats2half2_rn(0.125f, 0.125f);
    const uint32_t kbase = smem_u32(Ks) + (((lane >> 4) << 3) + (lane & 7)) * 144
                         + ((lane >> 3) & 1) * 16;
#pragma unroll
    for (int ks = 0; ks < 4; ks++) {
        const __half* qp = Qrow + (size_t)g * TRIPLE + ks * 16 + 2 * t4;
        uint32_t af[4];
        af[0] = *(const uint32_t*)qp;
        af[1] = *(const uint32_t*)(qp + 8 * TRIPLE);
        af[2] = *(const uint32_t*)(qp + 8);
        af[3] = *(const uint32_t*)(qp + 8 * TRIPLE + 8);
#pragma unroll
        for (int z = 0; z < 4; z++) {
            __half2 hv = __hmul2(*(__half2*)&af[z], qsc);
            af[z] = *(uint32_t*)&hv;
        }
#pragma unroll
        for (int jp = 0; jp < 12; jp++) {
            uint32_t bf[4];
            ldsm_x4(bf, kbase + jp * (16 * 144) + ks * 32);
            mma16816(s_acc[2*jp],   af[0],af[1],af[2],af[3], bf[0],bf[1]);
            mma16816(s_acc[2*jp+1], af[0],af[1],af[2],af[3], bf[2],bf[3]);
        }
    }

    // ---- masking ----
    const int rq0 = warp * 16 + g;
    const int rq1 = rq0 + 8;
#pragma unroll
    for (int jt = 0; jt < 16; jt++) {
        int c = jt * 8 + 2 * t4;
        if (!smask[c])   { s_acc[jt][0] = -1e30f; s_acc[jt][2] = -1e30f; }
        if (!smask[c+1]) { s_acc[jt][1] = -1e30f; s_acc[jt][3] = -1e30f; }
    }
#pragma unroll
    for (int jt = 16; jt < 24; jt++) {
        int c = (jt - 16) * 8 + 2 * t4;
        if (c     > rq0) s_acc[jt][0] = -1e30f;
        if (c + 1 > rq0) s_acc[jt][1] = -1e30f;
        if (c     > rq1) s_acc[jt][2] = -1e30f;
        if (c + 1 > rq1) s_acc[jt][3] = -1e30f;
    }

    // ---- row max ----
    float mx0 = -1e30f, mx1 = -1e30f;
#pragma unroll
    for (int jt = 0; jt < 24; jt++) {
        mx0 = fmaxf(mx0, fmaxf(s_acc[jt][0], s_acc[jt][1]));
        mx1 = fmaxf(mx1, fmaxf(s_acc[jt][2], s_acc[jt][3]));
    }
    mx0 = fmaxf(mx0, __shfl_xor_sync(0xffffffffu, mx0, 1));
    mx0 = fmaxf(mx0, __shfl_xor_sync(0xffffffffu, mx0, 2));
    mx1 = fmaxf(mx1, __shfl_xor_sync(0xffffffffu, mx1, 1));
    mx1 = fmaxf(mx1, __shfl_xor_sync(0xffffffffu, mx1, 2));

    // ---- P = exp2(S*log2e - mx*log2e) packed fp16 ----
    const float L2E = 1.44269504f;
    const float c0 = mx0 * L2E, c1 = mx1 * L2E;
    uint32_t p_lo[24], p_hi[24];
#pragma unroll
    for (int jt = 0; jt < 24; jt++) {
        float f0 = fmaf(s_acc[jt][0], L2E, -c0);
        float f1 = fmaf(s_acc[jt][1], L2E, -c0);
        float f2 = fmaf(s_acc[jt][2], L2E, -c1);
        float f3 = fmaf(s_acc[jt][3], L2E, -c1);
        p_lo[jt] = ex2_f16x2(pack_f16x2(f0, f1));
        p_hi[jt] = ex2_f16x2(pack_f16x2(f2, f3));
    }

    // ---- O = P V  (tile 8 = ones -> row sums) ----
    float o[9][4];
#pragma unroll
    for (int nt = 0; nt < 9; nt++)
#pragma unroll
        for (int r = 0; r < 4; r++) o[nt][r] = 0.f;

    const uint32_t vbase = smem_u32(Vs) + ((((lane >> 3) & 1) * 8) + (lane & 7)) * 144
                         + (lane >> 4) * 16;
    const uint32_t vones = smem_u32(Vs) + ((((lane >> 3) & 1) * 8) + (lane & 7)) * 144 + 128;
#pragma unroll
    for (int kt = 0; kt < 12; kt++) {
        uint32_t a0 = p_lo[2*kt], a1 = p_hi[2*kt], a2 = p_lo[2*kt+1], a3 = p_hi[2*kt+1];
#pragma unroll
        for (int np = 0; np < 4; np++) {
            uint32_t bf[4];
            ldsm_x4_t(bf, vbase + kt * (16 * 144) + np * 32);
            mma16816(o[2*np],   a0,a1,a2,a3, bf[0],bf[1]);
            mma16816(o[2*np+1], a0,a1,a2,a3, bf[2],bf[3]);
        }
        uint32_t bo[2];
        ldsm_x2_t(bo, vones + kt * (16 * 144));
        mma16816(o[8], a0,a1,a2,a3, bo[0],bo[1]);
    }

    // ---- epilogue: divide by sum, store fp16 into g_a ----
    const float inv0 = 1.f / o[8][0];
    const float inv1 = 1.f / o[8][2];
    const size_t row0 = ((size_t)(b * NP + TEXTL + xr * 64 + rq0)) * KTOT + h * DHEAD;
    const size_t row1 = row0 + 8 * KTOT;
#pragma unroll
    for (int nt = 0; nt < 8; nt++) {
        int c = nt * 8 + 2 * t4;
        *(__half2*)&g_a[row0 + c] = __floats2half2_rn(o[nt][0] * inv0, o[nt][1] * inv0);
        *(__half2*)&g_a[row1 + c] = __floats2half2_rn(o[nt][2] * inv1, o[nt][3] * inv1);
    }
}

// ---------------------------------------------------------------------------
// Launch
// ---------------------------------------------------------------------------
extern "C" void kernel_launch(void* const* d_in, const int* in_sizes, int n_in,
                              void* d_out, int out_size)
{
    const float* x     = nullptr;
    const void*  mask  = nullptr;
    const float* w_qkv = nullptr;
    const float* w_out = nullptr;
    for (int i = 0; i < n_in; i++) {
        long long sz = in_sizes[i];
        if      (sz == (long long)BATCH * NSEQ * DIMC) x     = (const float*)d_in[i];
        else if (sz == BATCH * TEXTL)                  mask  = d_in[i];
        else if (sz == (long long)DIMC * TRIPLE)       w_qkv = (const float*)d_in[i];
        else if (sz == (long long)DIMC * DIMC)         w_out = (const float*)d_in[i];
    }

    __half *a, *bq, *bo, *qkvh;
    cudaGetSymbolAddress((void**)&a,    g_a);
    cudaGetSymbolAddress((void**)&bq,   g_b_qkv);
    cudaGetSymbolAddress((void**)&bo,   g_b_out);
    cudaGetSymbolAddress((void**)&qkvh, g_qkvh);

    cudaFuncSetAttribute(attn_kernel, cudaFuncAttributeMaxDynamicSharedMemorySize, SMEM_ATT);
    cudaFuncSetAttribute((const void*)gemm_fp16_kernel<TRIPLE, false, true>,
                         cudaFuncAttributeMaxDynamicSharedMemorySize, SMEM_GEMM);
    cudaFuncSetAttribute((const void*)gemm_fp16_kernel<DIMC, true, false>,
                         cudaFuncAttributeMaxDynamicSharedMemorySize, SMEM_GEMM);

    prep_kernel<<<PREP_N, 256>>>(x, w_qkv, w_out, mask);

    dim3 g1(TRIPLE / 128, MROWS / 128);  // 24 x 264
    gemm_fp16_kernel<TRIPLE, false, true><<<g1, 256, SMEM_GEMM>>>(a, bq, qkvh);

    attn_kernel<<<128 + BATCH * NHEAD * IMGDIM, 128, SMEM_ATT>>>();

    dim3 g2(DIMC / 128, MROWS / 128);    // 8 x 264
    gemm_fp16_kernel<DIMC, true, false><<<g2, 256, SMEM_GEMM>>>(a, bo, d_out);
}